// round 4
// baseline (speedup 1.0000x reference)
#include <cuda_runtime.h>
#include <cuda_bf16.h>
#include <math.h>

// Problem constants
#define B_   4
#define S_   2048
#define D_   1024
#define H_   16
#define DK_  64
#define M_ROWS (B_ * S_)      // 8192

// ---------------------------------------------------------------------------
// Scratch (device globals; no allocation allowed)
// ---------------------------------------------------------------------------
__device__ float g_q[(size_t)B_ * H_ * S_ * DK_];     // [B,H,S,dk]
__device__ float g_k[(size_t)B_ * H_ * S_ * DK_];
__device__ float g_v[(size_t)B_ * H_ * S_ * DK_];
__device__ float g_ctx[(size_t)B_ * S_ * D_];         // [B,S,D] (= [B,S,H,dk])

// ---------------------------------------------------------------------------
// NT GEMM: C[M,N] = A[M,K] * B[N,K]^T  (both K-major, i.e. x @ W.T)
// MODE 1: scatter output into [B,H,S,dk] (QKV projections)
// MODE 2: plain row-major + bias (output projection)
// 128x128 block tile, BK=8, 256 threads, 8x8 per thread, double-buffered smem.
// ---------------------------------------------------------------------------
#define GBM 128
#define GBN 128
#define GBK 8

template <int MODE>
__global__ __launch_bounds__(256)
void gemm_nt(const float* __restrict__ A, const float* __restrict__ Bw,
             const float* __restrict__ bias, float* __restrict__ C,
             int M, int N, int K)
{
    __shared__ float As[2][GBK][GBM];
    __shared__ float Bs[2][GBK][GBN];

    const int tid = threadIdx.x;
    const int tx = tid & 15;          // 0..15 -> N sub-tile
    const int ty = tid >> 4;          // 0..15 -> M sub-tile
    const int loadRow = tid >> 1;     // 0..127
    const int loadCol = (tid & 1) << 2; // 0 or 4

    const int mBase = blockIdx.y * GBM;
    const int nBase = blockIdx.x * GBN;

    const float* Ap = A + (size_t)(mBase + loadRow) * K + loadCol;
    const float* Bp = Bw + (size_t)(nBase + loadRow) * K + loadCol;

    // prefetch tile 0
    float4 ar = *(const float4*)Ap;
    float4 br = *(const float4*)Bp;
    As[0][loadCol + 0][loadRow] = ar.x;
    As[0][loadCol + 1][loadRow] = ar.y;
    As[0][loadCol + 2][loadRow] = ar.z;
    As[0][loadCol + 3][loadRow] = ar.w;
    Bs[0][loadCol + 0][loadRow] = br.x;
    Bs[0][loadCol + 1][loadRow] = br.y;
    Bs[0][loadCol + 2][loadRow] = br.z;
    Bs[0][loadCol + 3][loadRow] = br.w;
    __syncthreads();

    float acc[8][8];
#pragma unroll
    for (int i = 0; i < 8; ++i)
#pragma unroll
        for (int j = 0; j < 8; ++j) acc[i][j] = 0.0f;

    const int KT = K / GBK;
    for (int kt = 0; kt < KT; ++kt) {
        const int cur = kt & 1;
        if (kt + 1 < KT) {
            ar = *(const float4*)(Ap + (size_t)(kt + 1) * GBK);
            br = *(const float4*)(Bp + (size_t)(kt + 1) * GBK);
        }
#pragma unroll
        for (int k = 0; k < GBK; ++k) {
            float4 a0 = *(const float4*)&As[cur][k][ty * 8];
            float4 a1 = *(const float4*)&As[cur][k][ty * 8 + 4];
            float4 b0 = *(const float4*)&Bs[cur][k][tx * 8];
            float4 b1 = *(const float4*)&Bs[cur][k][tx * 8 + 4];
            float af[8] = {a0.x, a0.y, a0.z, a0.w, a1.x, a1.y, a1.z, a1.w};
            float bf[8] = {b0.x, b0.y, b0.z, b0.w, b1.x, b1.y, b1.z, b1.w};
#pragma unroll
            for (int i = 0; i < 8; ++i)
#pragma unroll
                for (int j = 0; j < 8; ++j)
                    acc[i][j] += af[i] * bf[j];
        }
        if (kt + 1 < KT) {
            const int nxt = cur ^ 1;
            As[nxt][loadCol + 0][loadRow] = ar.x;
            As[nxt][loadCol + 1][loadRow] = ar.y;
            As[nxt][loadCol + 2][loadRow] = ar.z;
            As[nxt][loadCol + 3][loadRow] = ar.w;
            Bs[nxt][loadCol + 0][loadRow] = br.x;
            Bs[nxt][loadCol + 1][loadRow] = br.y;
            Bs[nxt][loadCol + 2][loadRow] = br.z;
            Bs[nxt][loadCol + 3][loadRow] = br.w;
        }
        __syncthreads();
    }

    // Epilogue
#pragma unroll
    for (int i = 0; i < 8; ++i) {
        const int row = mBase + ty * 8 + i;
#pragma unroll
        for (int j = 0; j < 8; ++j) {
            const int col = nBase + tx * 8 + j;
            float v = acc[i][j];
            if (MODE == 2) {
                v += bias[col];
                C[(size_t)row * N + col] = v;
            } else {
                // scatter into [B,H,S,dk]
                const int b = row >> 11;        // row / 2048
                const int s = row & 2047;
                const int h = col >> 6;         // col / 64
                const int d = col & 63;
                C[(((size_t)(b * H_ + h)) * S_ + s) * DK_ + d] = v;
            }
        }
    }
}

// ---------------------------------------------------------------------------
// Attention: per (b,h), flash-style with online softmax.
// Block = 64 queries x full dk=64. 256 threads (16x16), 4x4 per thread.
// Loops over 32 key tiles of 64. Q,K stored [d][i] transposed; V [k][j]; P [i][k].
// ---------------------------------------------------------------------------
#define ATT_SMEM ((64*64 + 64*68 + 64*64 + 64*68) * 4)  // 67584 bytes

__global__ __launch_bounds__(256)
void attn_kernel(const float* __restrict__ Qg, const float* __restrict__ Kg,
                 const float* __restrict__ Vg, float* __restrict__ ctx)
{
    extern __shared__ float sm[];
    float* Qs = sm;                   // [64][64] transposed: Qs[d*64+i]
    float* Ks = Qs + 64 * 64;         // [64][68] transposed: Ks[d*68+j]
    float* Vs = Ks + 64 * 68;         // [64][64] natural:    Vs[k*64+j]
    float* Ps = Vs + 64 * 64;         // [64][68] natural:    Ps[i*68+k]

    const int tid = threadIdx.x;
    const int tx = tid & 15;
    const int ty = tid >> 4;
    const int bh = blockIdx.y;        // 0..63
    const int qt = blockIdx.x;        // 0..31

    const float* Qb = Qg + ((size_t)bh * S_ + qt * 64) * DK_;
    const float* Kb = Kg + (size_t)bh * S_ * DK_;
    const float* Vb = Vg + (size_t)bh * S_ * DK_;

    // Load Q tile transposed
    {
        const int i = tid >> 2;            // 0..63
        const int d0 = (tid & 3) * 16;     // 0,16,32,48
        const float4* src = (const float4*)(Qb + (size_t)i * DK_ + d0);
#pragma unroll
        for (int g = 0; g < 4; ++g) {
            float4 v = src[g];
            Qs[(d0 + g * 4 + 0) * 64 + i] = v.x;
            Qs[(d0 + g * 4 + 1) * 64 + i] = v.y;
            Qs[(d0 + g * 4 + 2) * 64 + i] = v.z;
            Qs[(d0 + g * 4 + 3) * 64 + i] = v.w;
        }
    }

    float mrow[4], lrow[4], acc[4][4];
#pragma unroll
    for (int ii = 0; ii < 4; ++ii) {
        mrow[ii] = -INFINITY;
        lrow[ii] = 0.0f;
#pragma unroll
        for (int jj = 0; jj < 4; ++jj) acc[ii][jj] = 0.0f;
    }

    for (int kt = 0; kt < S_ / 64; ++kt) {
        __syncthreads();   // prior-iteration readers of Ks/Vs/Ps done (also covers Qs on kt=0)
        // stage K (transposed) and V (natural)
        {
            const int i = tid >> 2;
            const int d0 = (tid & 3) * 16;
            const float4* ks = (const float4*)(Kb + (size_t)(kt * 64 + i) * DK_ + d0);
#pragma unroll
            for (int g = 0; g < 4; ++g) {
                float4 v = ks[g];
                Ks[(d0 + g * 4 + 0) * 68 + i] = v.x;
                Ks[(d0 + g * 4 + 1) * 68 + i] = v.y;
                Ks[(d0 + g * 4 + 2) * 68 + i] = v.z;
                Ks[(d0 + g * 4 + 3) * 68 + i] = v.w;
            }
            const float4* vsrc = (const float4*)(Vb + (size_t)(kt * 64 + i) * DK_ + d0);
            float4* vdst = (float4*)(Vs + i * 64 + d0);
#pragma unroll
            for (int g = 0; g < 4; ++g) vdst[g] = vsrc[g];
        }
        __syncthreads();

        // S = Q K^T (4x4 per thread)
        float s[4][4];
#pragma unroll
        for (int ii = 0; ii < 4; ++ii)
#pragma unroll
            for (int jj = 0; jj < 4; ++jj) s[ii][jj] = 0.0f;

#pragma unroll 16
        for (int d = 0; d < 64; ++d) {
            float4 a = *(const float4*)(Qs + d * 64 + ty * 4);
            float4 b = *(const float4*)(Ks + d * 68 + tx * 4);
            s[0][0] += a.x * b.x; s[0][1] += a.x * b.y; s[0][2] += a.x * b.z; s[0][3] += a.x * b.w;
            s[1][0] += a.y * b.x; s[1][1] += a.y * b.y; s[1][2] += a.y * b.z; s[1][3] += a.y * b.w;
            s[2][0] += a.z * b.x; s[2][1] += a.z * b.y; s[2][2] += a.z * b.z; s[2][3] += a.z * b.w;
            s[3][0] += a.w * b.x; s[3][1] += a.w * b.y; s[3][2] += a.w * b.z; s[3][3] += a.w * b.w;
        }

        // Online softmax (scale 1/sqrt(64) = 0.125)
#pragma unroll
        for (int ii = 0; ii < 4; ++ii) {
            float v0 = s[ii][0] * 0.125f;
            float v1 = s[ii][1] * 0.125f;
            float v2 = s[ii][2] * 0.125f;
            float v3 = s[ii][3] * 0.125f;
            float rmax = fmaxf(fmaxf(v0, v1), fmaxf(v2, v3));
            rmax = fmaxf(rmax, __shfl_xor_sync(0xffffffffu, rmax, 1));
            rmax = fmaxf(rmax, __shfl_xor_sync(0xffffffffu, rmax, 2));
            rmax = fmaxf(rmax, __shfl_xor_sync(0xffffffffu, rmax, 4));
            rmax = fmaxf(rmax, __shfl_xor_sync(0xffffffffu, rmax, 8));
            const float mnew = fmaxf(mrow[ii], rmax);
            const float corr = __expf(mrow[ii] - mnew);
            float p0 = __expf(v0 - mnew);
            float p1 = __expf(v1 - mnew);
            float p2 = __expf(v2 - mnew);
            float p3 = __expf(v3 - mnew);
            float rsum = p0 + p1 + p2 + p3;
            rsum += __shfl_xor_sync(0xffffffffu, rsum, 1);
            rsum += __shfl_xor_sync(0xffffffffu, rsum, 2);
            rsum += __shfl_xor_sync(0xffffffffu, rsum, 4);
            rsum += __shfl_xor_sync(0xffffffffu, rsum, 8);
            lrow[ii] = lrow[ii] * corr + rsum;
            mrow[ii] = mnew;
            acc[ii][0] *= corr; acc[ii][1] *= corr; acc[ii][2] *= corr; acc[ii][3] *= corr;
            s[ii][0] = p0; s[ii][1] = p1; s[ii][2] = p2; s[ii][3] = p3;
        }

        // write P tile
#pragma unroll
        for (int ii = 0; ii < 4; ++ii)
#pragma unroll
            for (int jj = 0; jj < 4; ++jj)
                Ps[(ty * 4 + ii) * 68 + tx * 4 + jj] = s[ii][jj];
        __syncthreads();

        // acc += P @ V
#pragma unroll 16
        for (int k = 0; k < 64; ++k) {
            float4 b = *(const float4*)(Vs + k * 64 + tx * 4);
            float a0 = Ps[(ty * 4 + 0) * 68 + k];
            float a1 = Ps[(ty * 4 + 1) * 68 + k];
            float a2 = Ps[(ty * 4 + 2) * 68 + k];
            float a3 = Ps[(ty * 4 + 3) * 68 + k];
            acc[0][0] += a0 * b.x; acc[0][1] += a0 * b.y; acc[0][2] += a0 * b.z; acc[0][3] += a0 * b.w;
            acc[1][0] += a1 * b.x; acc[1][1] += a1 * b.y; acc[1][2] += a1 * b.z; acc[1][3] += a1 * b.w;
            acc[2][0] += a2 * b.x; acc[2][1] += a2 * b.y; acc[2][2] += a2 * b.z; acc[2][3] += a2 * b.w;
            acc[3][0] += a3 * b.x; acc[3][1] += a3 * b.y; acc[3][2] += a3 * b.z; acc[3][3] += a3 * b.w;
        }
    }

    // Epilogue: normalize and scatter to ctx [B,S,H,dk]
    const int bb = bh >> 4;
    const int h = bh & 15;
#pragma unroll
    for (int ii = 0; ii < 4; ++ii) {
        const int srow = qt * 64 + ty * 4 + ii;
        const float inv = 1.0f / lrow[ii];
        float4 o;
        o.x = acc[ii][0] * inv;
        o.y = acc[ii][1] * inv;
        o.z = acc[ii][2] * inv;
        o.w = acc[ii][3] * inv;
        *(float4*)(ctx + (((size_t)bb * S_ + srow) * H_ + h) * DK_ + tx * 4) = o;
    }
}

// ---------------------------------------------------------------------------
// Launcher
// ---------------------------------------------------------------------------
extern "C" void kernel_launch(void* const* d_in, const int* in_sizes, int n_in,
                              void* d_out, int out_size)
{
    const float* query = (const float*)d_in[0];
    const float* key_  = (const float*)d_in[1];
    const float* value = (const float*)d_in[2];
    const float* w_q   = (const float*)d_in[3];
    const float* w_k   = (const float*)d_in[4];
    const float* w_v   = (const float*)d_in[5];
    const float* w_o   = (const float*)d_in[6];
    const float* b_o   = (const float*)d_in[7];
    float* out = (float*)d_out;

    float *gq, *gk, *gv, *gctx;
    cudaGetSymbolAddress((void**)&gq, g_q);
    cudaGetSymbolAddress((void**)&gk, g_k);
    cudaGetSymbolAddress((void**)&gv, g_v);
    cudaGetSymbolAddress((void**)&gctx, g_ctx);

    cudaFuncSetAttribute(attn_kernel, cudaFuncAttributeMaxDynamicSharedMemorySize, ATT_SMEM);

    dim3 gGemm(D_ / GBN, M_ROWS / GBM);   // (8, 64)
    dim3 bGemm(256);

    gemm_nt<1><<<gGemm, bGemm>>>(query, w_q, nullptr, gq, M_ROWS, D_, D_);
    gemm_nt<1><<<gGemm, bGemm>>>(key_,  w_k, nullptr, gk, M_ROWS, D_, D_);
    gemm_nt<1><<<gGemm, bGemm>>>(value, w_v, nullptr, gv, M_ROWS, D_, D_);

    dim3 gAtt(S_ / 64, B_ * H_);          // (32, 64)
    attn_kernel<<<gAtt, 256, ATT_SMEM>>>(gq, gk, gv, gctx);

    gemm_nt<2><<<gGemm, bGemm>>>(gctx, w_o, b_o, out, M_ROWS, D_, D_);
}

// round 8
// speedup vs baseline: 1.3427x; 1.3427x over previous
#include <cuda_runtime.h>
#include <cuda_bf16.h>
#include <math.h>
#include <stdint.h>

// Problem constants
#define B_   4
#define S_   2048
#define D_   1024
#define H_   16
#define DK_  64
#define M_ROWS (B_ * S_)      // 8192

// ---------------------------------------------------------------------------
// Scratch (device globals; no allocation allowed)
// ---------------------------------------------------------------------------
__device__ float g_q[(size_t)B_ * H_ * S_ * DK_];     // [B,H,S,dk]
__device__ float g_k[(size_t)B_ * H_ * S_ * DK_];
__device__ float g_v[(size_t)B_ * H_ * S_ * DK_];
__device__ float g_ctx[(size_t)B_ * S_ * D_];         // [B,S,D]
__device__ __nv_bfloat16 g_ah[(size_t)M_ROWS * D_];   // activation hi
__device__ __nv_bfloat16 g_al[(size_t)M_ROWS * D_];   // activation lo
__device__ __nv_bfloat16 g_wh[(size_t)D_ * D_];       // weight hi
__device__ __nv_bfloat16 g_wl[(size_t)D_ * D_];       // weight lo

// ---------------------------------------------------------------------------
// Helpers (baseline PTX only — NO tcgen05; harness targets plain sm_103)
// ---------------------------------------------------------------------------
__device__ __forceinline__ uint32_t smem_u32(const void* p) {
    uint32_t a;
    asm("{ .reg .u64 t; cvta.to.shared.u64 t, %1; cvt.u32.u64 %0, t; }"
        : "=r"(a) : "l"(p));
    return a;
}

__device__ __forceinline__ void cp16(uint32_t dst, const void* src) {
    asm volatile("cp.async.cg.shared.global [%0], [%1], 16;" :: "r"(dst), "l"(src));
}

__device__ __forceinline__ void ldm4(uint32_t* r, uint32_t addr) {
    asm volatile("ldmatrix.sync.aligned.m8n8.x4.shared.b16 {%0,%1,%2,%3}, [%4];"
                 : "=r"(r[0]), "=r"(r[1]), "=r"(r[2]), "=r"(r[3]) : "r"(addr));
}

__device__ __forceinline__ void mma16816(float* d, const uint32_t* a, const uint32_t* b) {
    asm volatile(
        "mma.sync.aligned.m16n8k16.row.col.f32.bf16.bf16.f32 "
        "{%0,%1,%2,%3}, {%4,%5,%6,%7}, {%8,%9}, {%0,%1,%2,%3};"
        : "+f"(d[0]), "+f"(d[1]), "+f"(d[2]), "+f"(d[3])
        : "r"(a[0]), "r"(a[1]), "r"(a[2]), "r"(a[3]), "r"(b[0]), "r"(b[1]));
}

// ---------------------------------------------------------------------------
// fp32 -> (hi, lo) bf16 split
// ---------------------------------------------------------------------------
__global__ __launch_bounds__(256)
void split_bf16(const float* __restrict__ in, __nv_bfloat16* __restrict__ hi,
                __nv_bfloat16* __restrict__ lo, int n4)
{
    int i = blockIdx.x * blockDim.x + threadIdx.x;
    if (i >= n4) return;
    float4 v = ((const float4*)in)[i];
    __nv_bfloat16 h0 = __float2bfloat16(v.x);
    __nv_bfloat16 h1 = __float2bfloat16(v.y);
    __nv_bfloat16 h2 = __float2bfloat16(v.z);
    __nv_bfloat16 h3 = __float2bfloat16(v.w);
    __nv_bfloat16 l0 = __float2bfloat16(v.x - __bfloat162float(h0));
    __nv_bfloat16 l1 = __float2bfloat16(v.y - __bfloat162float(h1));
    __nv_bfloat16 l2 = __float2bfloat16(v.z - __bfloat162float(h2));
    __nv_bfloat16 l3 = __float2bfloat16(v.w - __bfloat162float(h3));
    __nv_bfloat162* hp = (__nv_bfloat162*)hi;
    __nv_bfloat162* lp = (__nv_bfloat162*)lo;
    __nv_bfloat162 a; a.x = h0; a.y = h1;
    __nv_bfloat162 b; b.x = h2; b.y = h3;
    __nv_bfloat162 c; c.x = l0; c.y = l1;
    __nv_bfloat162 d; d.x = l2; d.y = l3;
    hp[2 * i] = a; hp[2 * i + 1] = b;
    lp[2 * i] = c; lp[2 * i + 1] = d;
}

// ---------------------------------------------------------------------------
// HMMA (mma.sync bf16) NT GEMM with hi/lo split: C[M,N] = A[M,K]*B[N,K]^T, fp32 acc
// Tile 128x128, BK=32 bf16, 256 threads = 8 warps (2x4), warp tile 64x32.
// Smem rows padded to 40 elems (80B) -> conflict-free ldmatrix.
// MODE 1: scatter into [B,H,S,dk].  MODE 2: row-major + bias.
// ---------------------------------------------------------------------------
#define GSTRIDE 40                       // padded bf16 elems per smem row
#define MATB    (128 * GSTRIDE * 2)      // 10240 bytes per matrix
#define STAGEB  (4 * MATB)               // 40960 bytes per stage
#define GSMEM   (2 * STAGEB)             // 81920 bytes
#define NCHUNK  (D_ / 32)                // 32

template <int MODE>
__global__ __launch_bounds__(256)
void gemm_mma(const __nv_bfloat16* __restrict__ Ah, const __nv_bfloat16* __restrict__ Al,
              const __nv_bfloat16* __restrict__ Bh, const __nv_bfloat16* __restrict__ Bl,
              const float* __restrict__ bias, float* __restrict__ C)
{
    extern __shared__ char smc[];
    const uint32_t sb = smem_u32(smc);
    const int tid = threadIdx.x;
    const int lane = tid & 31;
    const int wid = tid >> 5;
    const int mBase = blockIdx.y * 128;
    const int nBase = blockIdx.x * 128;
    const int wm = (wid >> 2) * 64;      // warp M offset within tile
    const int wn = (wid & 3) * 32;       // warp N offset within tile

    // global loader mapping: thread -> (row 0..127, 2 consecutive 16B chunks)
    const int lrow = tid >> 1;
    const int lch = (tid & 1) * 2;       // 0 or 2 (16B units)
    const __nv_bfloat16* gAh = Ah + (size_t)(mBase + lrow) * D_ + lch * 8;
    const __nv_bfloat16* gAl = Al + (size_t)(mBase + lrow) * D_ + lch * 8;
    const __nv_bfloat16* gBh = Bh + (size_t)(nBase + lrow) * D_ + lch * 8;
    const __nv_bfloat16* gBl = Bl + (size_t)(nBase + lrow) * D_ + lch * 8;
    const uint32_t dsto = (uint32_t)(lrow * (GSTRIDE * 2) + lch * 16);

    float acc[4][4][4];
#pragma unroll
    for (int mi = 0; mi < 4; ++mi)
#pragma unroll
        for (int nj = 0; nj < 4; ++nj)
#pragma unroll
            for (int e = 0; e < 4; ++e) acc[mi][nj][e] = 0.0f;

    // ldmatrix address components (byte offsets inside a matrix)
    const uint32_t a_rc = (uint32_t)((wm + (lane & 15)) * (GSTRIDE * 2) + (lane >> 4) * 16);
    const uint32_t b_rc = (uint32_t)((wn + (lane >> 4) * 8 + (lane & 7)) * (GSTRIDE * 2)
                                     + ((lane >> 3) & 1) * 16);

    // prefetch chunk 0 into stage 0
    {
        const uint32_t s0 = sb;
        cp16(s0 + dsto,                 gAh);
        cp16(s0 + dsto + 16,            gAh + 8);
        cp16(s0 + MATB + dsto,          gAl);
        cp16(s0 + MATB + dsto + 16,     gAl + 8);
        cp16(s0 + 2 * MATB + dsto,      gBh);
        cp16(s0 + 2 * MATB + dsto + 16, gBh + 8);
        cp16(s0 + 3 * MATB + dsto,      gBl);
        cp16(s0 + 3 * MATB + dsto + 16, gBl + 8);
        asm volatile("cp.async.commit_group;" ::: "memory");
    }

    for (int c = 0; c < NCHUNK; ++c) {
        if (c + 1 < NCHUNK) {
            const uint32_t s0 = sb + ((c + 1) & 1) * STAGEB;
            const int kb = (c + 1) * 32;
            cp16(s0 + dsto,                 gAh + kb);
            cp16(s0 + dsto + 16,            gAh + kb + 8);
            cp16(s0 + MATB + dsto,          gAl + kb);
            cp16(s0 + MATB + dsto + 16,     gAl + kb + 8);
            cp16(s0 + 2 * MATB + dsto,      gBh + kb);
            cp16(s0 + 2 * MATB + dsto + 16, gBh + kb + 8);
            cp16(s0 + 3 * MATB + dsto,      gBl + kb);
            cp16(s0 + 3 * MATB + dsto + 16, gBl + kb + 8);
            asm volatile("cp.async.commit_group;" ::: "memory");
            asm volatile("cp.async.wait_group 1;" ::: "memory");
        } else {
            asm volatile("cp.async.wait_group 0;" ::: "memory");
        }
        __syncthreads();

        const uint32_t sAh = sb + (c & 1) * STAGEB;
        const uint32_t sAl = sAh + MATB;
        const uint32_t sBh = sAh + 2 * MATB;
        const uint32_t sBl = sAh + 3 * MATB;

#pragma unroll
        for (int ks = 0; ks < 2; ++ks) {
            const uint32_t kbyte = (uint32_t)(ks * 32);   // 16 bf16 = 32B

            uint32_t bh[2][4], bl[2][4];
#pragma unroll
            for (int nj = 0; nj < 2; ++nj) {
                const uint32_t boff = b_rc + kbyte + (uint32_t)(nj * 16 * GSTRIDE * 2);
                ldm4(bh[nj], sBh + boff);
                ldm4(bl[nj], sBl + boff);
            }

#pragma unroll
            for (int mi = 0; mi < 4; ++mi) {
                const uint32_t aoff = a_rc + kbyte + (uint32_t)(mi * 16 * GSTRIDE * 2);
                uint32_t ah[4], al[4];
                ldm4(ah, sAh + aoff);
                ldm4(al, sAl + aoff);
#pragma unroll
                for (int n8 = 0; n8 < 4; ++n8) {
                    const uint32_t* bhf = &bh[n8 >> 1][(n8 & 1) * 2];
                    const uint32_t* blf = &bl[n8 >> 1][(n8 & 1) * 2];
                    mma16816(acc[mi][n8], ah, bhf);   // Ah * Bh
                    mma16816(acc[mi][n8], al, bhf);   // Al * Bh
                    mma16816(acc[mi][n8], ah, blf);   // Ah * Bl
                }
            }
        }
        __syncthreads();
    }

    // Epilogue: c-fragment thread mapping (g = lane/4 row, 2*(lane%4) col)
    const int g = lane >> 2;
    const int i2 = (lane & 3) * 2;
#pragma unroll
    for (int mi = 0; mi < 4; ++mi) {
#pragma unroll
        for (int n8 = 0; n8 < 4; ++n8) {
            const int row0 = mBase + wm + mi * 16 + g;
            const int row1 = row0 + 8;
            const int col = nBase + wn + n8 * 8 + i2;
            float2 v0, v1;
            v0.x = acc[mi][n8][0]; v0.y = acc[mi][n8][1];
            v1.x = acc[mi][n8][2]; v1.y = acc[mi][n8][3];
            if (MODE == 2) {
                v0.x += bias[col]; v0.y += bias[col + 1];
                v1.x += bias[col]; v1.y += bias[col + 1];
                *(float2*)(C + (size_t)row0 * D_ + col) = v0;
                *(float2*)(C + (size_t)row1 * D_ + col) = v1;
            } else {
                // scatter into [B,H,S,dk]; col pair never crosses head boundary
                const int h = col >> 6;
                const int d0 = col & 63;
                const int b0i = row0 >> 11, s0i = row0 & 2047;
                const int b1i = row1 >> 11, s1i = row1 & 2047;
                *(float2*)(C + (((size_t)(b0i * H_ + h)) * S_ + s0i) * DK_ + d0) = v0;
                *(float2*)(C + (((size_t)(b1i * H_ + h)) * S_ + s1i) * DK_ + d0) = v1;
            }
        }
    }
}

// ---------------------------------------------------------------------------
// Attention: per (b,h), flash-style with online softmax (unchanged, passing).
// ---------------------------------------------------------------------------
#define ATT_SMEM ((64*64 + 64*68 + 64*64 + 64*68) * 4)  // 67584 bytes

__global__ __launch_bounds__(256)
void attn_kernel(const float* __restrict__ Qg, const float* __restrict__ Kg,
                 const float* __restrict__ Vg, float* __restrict__ ctx)
{
    extern __shared__ float sm[];
    float* Qs = sm;                   // [64][64] transposed: Qs[d*64+i]
    float* Ks = Qs + 64 * 64;         // [64][68] transposed: Ks[d*68+j]
    float* Vs = Ks + 64 * 68;         // [64][64] natural:    Vs[k*64+j]
    float* Ps = Vs + 64 * 64;         // [64][68] natural:    Ps[i*68+k]

    const int tid = threadIdx.x;
    const int tx = tid & 15;
    const int ty = tid >> 4;
    const int bh = blockIdx.y;        // 0..63
    const int qt = blockIdx.x;        // 0..31

    const float* Qb = Qg + ((size_t)bh * S_ + qt * 64) * DK_;
    const float* Kb = Kg + (size_t)bh * S_ * DK_;
    const float* Vb = Vg + (size_t)bh * S_ * DK_;

    // Load Q tile transposed
    {
        const int i = tid >> 2;            // 0..63
        const int d0 = (tid & 3) * 16;     // 0,16,32,48
        const float4* src = (const float4*)(Qb + (size_t)i * DK_ + d0);
#pragma unroll
        for (int g = 0; g < 4; ++g) {
            float4 v = src[g];
            Qs[(d0 + g * 4 + 0) * 64 + i] = v.x;
            Qs[(d0 + g * 4 + 1) * 64 + i] = v.y;
            Qs[(d0 + g * 4 + 2) * 64 + i] = v.z;
            Qs[(d0 + g * 4 + 3) * 64 + i] = v.w;
        }
    }

    float mrow[4], lrow[4], acc[4][4];
#pragma unroll
    for (int ii = 0; ii < 4; ++ii) {
        mrow[ii] = -INFINITY;
        lrow[ii] = 0.0f;
#pragma unroll
        for (int jj = 0; jj < 4; ++jj) acc[ii][jj] = 0.0f;
    }

    for (int kt = 0; kt < S_ / 64; ++kt) {
        __syncthreads();
        // stage K (transposed) and V (natural)
        {
            const int i = tid >> 2;
            const int d0 = (tid & 3) * 16;
            const float4* ks = (const float4*)(Kb + (size_t)(kt * 64 + i) * DK_ + d0);
#pragma unroll
            for (int g = 0; g < 4; ++g) {
                float4 v = ks[g];
                Ks[(d0 + g * 4 + 0) * 68 + i] = v.x;
                Ks[(d0 + g * 4 + 1) * 68 + i] = v.y;
                Ks[(d0 + g * 4 + 2) * 68 + i] = v.z;
                Ks[(d0 + g * 4 + 3) * 68 + i] = v.w;
            }
            const float4* vsrc = (const float4*)(Vb + (size_t)(kt * 64 + i) * DK_ + d0);
            float4* vdst = (float4*)(Vs + i * 64 + d0);
#pragma unroll
            for (int g = 0; g < 4; ++g) vdst[g] = vsrc[g];
        }
        __syncthreads();

        // S = Q K^T
        float s[4][4];
#pragma unroll
        for (int ii = 0; ii < 4; ++ii)
#pragma unroll
            for (int jj = 0; jj < 4; ++jj) s[ii][jj] = 0.0f;

#pragma unroll 16
        for (int d = 0; d < 64; ++d) {
            float4 a = *(const float4*)(Qs + d * 64 + ty * 4);
            float4 b = *(const float4*)(Ks + d * 68 + tx * 4);
            s[0][0] += a.x * b.x; s[0][1] += a.x * b.y; s[0][2] += a.x * b.z; s[0][3] += a.x * b.w;
            s[1][0] += a.y * b.x; s[1][1] += a.y * b.y; s[1][2] += a.y * b.z; s[1][3] += a.y * b.w;
            s[2][0] += a.z * b.x; s[2][1] += a.z * b.y; s[2][2] += a.z * b.z; s[2][3] += a.z * b.w;
            s[3][0] += a.w * b.x; s[3][1] += a.w * b.y; s[3][2] += a.w * b.z; s[3][3] += a.w * b.w;
        }

        // Online softmax (scale 1/8)
#pragma unroll
        for (int ii = 0; ii < 4; ++ii) {
            float v0 = s[ii][0] * 0.125f;
            float v1 = s[ii][1] * 0.125f;
            float v2 = s[ii][2] * 0.125f;
            float v3 = s[ii][3] * 0.125f;
            float rmax = fmaxf(fmaxf(v0, v1), fmaxf(v2, v3));
            rmax = fmaxf(rmax, __shfl_xor_sync(0xffffffffu, rmax, 1));
            rmax = fmaxf(rmax, __shfl_xor_sync(0xffffffffu, rmax, 2));
            rmax = fmaxf(rmax, __shfl_xor_sync(0xffffffffu, rmax, 4));
            rmax = fmaxf(rmax, __shfl_xor_sync(0xffffffffu, rmax, 8));
            const float mnew = fmaxf(mrow[ii], rmax);
            const float corr = __expf(mrow[ii] - mnew);
            float p0 = __expf(v0 - mnew);
            float p1 = __expf(v1 - mnew);
            float p2 = __expf(v2 - mnew);
            float p3 = __expf(v3 - mnew);
            float rsum = p0 + p1 + p2 + p3;
            rsum += __shfl_xor_sync(0xffffffffu, rsum, 1);
            rsum += __shfl_xor_sync(0xffffffffu, rsum, 2);
            rsum += __shfl_xor_sync(0xffffffffu, rsum, 4);
            rsum += __shfl_xor_sync(0xffffffffu, rsum, 8);
            lrow[ii] = lrow[ii] * corr + rsum;
            mrow[ii] = mnew;
            acc[ii][0] *= corr; acc[ii][1] *= corr; acc[ii][2] *= corr; acc[ii][3] *= corr;
            s[ii][0] = p0; s[ii][1] = p1; s[ii][2] = p2; s[ii][3] = p3;
        }

        // write P tile
#pragma unroll
        for (int ii = 0; ii < 4; ++ii)
#pragma unroll
            for (int jj = 0; jj < 4; ++jj)
                Ps[(ty * 4 + ii) * 68 + tx * 4 + jj] = s[ii][jj];
        __syncthreads();

        // acc += P @ V
#pragma unroll 16
        for (int k = 0; k < 64; ++k) {
            float4 b = *(const float4*)(Vs + k * 64 + tx * 4);
            float a0 = Ps[(ty * 4 + 0) * 68 + k];
            float a1 = Ps[(ty * 4 + 1) * 68 + k];
            float a2 = Ps[(ty * 4 + 2) * 68 + k];
            float a3 = Ps[(ty * 4 + 3) * 68 + k];
            acc[0][0] += a0 * b.x; acc[0][1] += a0 * b.y; acc[0][2] += a0 * b.z; acc[0][3] += a0 * b.w;
            acc[1][0] += a1 * b.x; acc[1][1] += a1 * b.y; acc[1][2] += a1 * b.z; acc[1][3] += a1 * b.w;
            acc[2][0] += a2 * b.x; acc[2][1] += a2 * b.y; acc[2][2] += a2 * b.z; acc[2][3] += a2 * b.w;
            acc[3][0] += a3 * b.x; acc[3][1] += a3 * b.y; acc[3][2] += a3 * b.z; acc[3][3] += a3 * b.w;
        }
    }

    // Epilogue: normalize and scatter to ctx [B,S,H,dk]
    const int bb = bh >> 4;
    const int h = bh & 15;
#pragma unroll
    for (int ii = 0; ii < 4; ++ii) {
        const int srow = qt * 64 + ty * 4 + ii;
        const float inv = 1.0f / lrow[ii];
        float4 o;
        o.x = acc[ii][0] * inv;
        o.y = acc[ii][1] * inv;
        o.z = acc[ii][2] * inv;
        o.w = acc[ii][3] * inv;
        *(float4*)(ctx + (((size_t)bb * S_ + srow) * H_ + h) * DK_ + tx * 4) = o;
    }
}

// ---------------------------------------------------------------------------
// Launcher
// ---------------------------------------------------------------------------
extern "C" void kernel_launch(void* const* d_in, const int* in_sizes, int n_in,
                              void* d_out, int out_size)
{
    const float* query = (const float*)d_in[0];
    const float* key_  = (const float*)d_in[1];
    const float* value = (const float*)d_in[2];
    const float* w_q   = (const float*)d_in[3];
    const float* w_k   = (const float*)d_in[4];
    const float* w_v   = (const float*)d_in[5];
    const float* w_o   = (const float*)d_in[6];
    const float* b_o   = (const float*)d_in[7];
    float* out = (float*)d_out;

    float *gq, *gk, *gv, *gctx;
    __nv_bfloat16 *ah, *al, *wh, *wl;
    cudaGetSymbolAddress((void**)&gq, g_q);
    cudaGetSymbolAddress((void**)&gk, g_k);
    cudaGetSymbolAddress((void**)&gv, g_v);
    cudaGetSymbolAddress((void**)&gctx, g_ctx);
    cudaGetSymbolAddress((void**)&ah, g_ah);
    cudaGetSymbolAddress((void**)&al, g_al);
    cudaGetSymbolAddress((void**)&wh, g_wh);
    cudaGetSymbolAddress((void**)&wl, g_wl);

    cudaFuncSetAttribute(attn_kernel, cudaFuncAttributeMaxDynamicSharedMemorySize, ATT_SMEM);
    cudaFuncSetAttribute(gemm_mma<1>, cudaFuncAttributeMaxDynamicSharedMemorySize, GSMEM);
    cudaFuncSetAttribute(gemm_mma<2>, cudaFuncAttributeMaxDynamicSharedMemorySize, GSMEM);

    const int actN4 = (M_ROWS * D_) / 4;   // 2097152
    const int wN4   = (D_ * D_) / 4;       // 262144
    dim3 gGemm(D_ / 128, M_ROWS / 128);    // (8, 64)

    // Q projection
    split_bf16<<<(actN4 + 255) / 256, 256>>>(query, ah, al, actN4);
    split_bf16<<<(wN4 + 255) / 256, 256>>>(w_q, wh, wl, wN4);
    gemm_mma<1><<<gGemm, 256, GSMEM>>>(ah, al, wh, wl, nullptr, gq);

    // K projection
    split_bf16<<<(actN4 + 255) / 256, 256>>>(key_, ah, al, actN4);
    split_bf16<<<(wN4 + 255) / 256, 256>>>(w_k, wh, wl, wN4);
    gemm_mma<1><<<gGemm, 256, GSMEM>>>(ah, al, wh, wl, nullptr, gk);

    // V projection
    split_bf16<<<(actN4 + 255) / 256, 256>>>(value, ah, al, actN4);
    split_bf16<<<(wN4 + 255) / 256, 256>>>(w_v, wh, wl, wN4);
    gemm_mma<1><<<gGemm, 256, GSMEM>>>(ah, al, wh, wl, nullptr, gv);

    // Attention
    dim3 gAtt(S_ / 64, B_ * H_);          // (32, 64)
    attn_kernel<<<gAtt, 256, ATT_SMEM>>>(gq, gk, gv, gctx);

    // Output projection + bias
    split_bf16<<<(actN4 + 255) / 256, 256>>>(gctx, ah, al, actN4);
    split_bf16<<<(wN4 + 255) / 256, 256>>>(w_o, wh, wl, wN4);
    gemm_mma<2><<<gGemm, 256, GSMEM>>>(ah, al, wh, wl, b_o, out);
}

// round 9
// speedup vs baseline: 2.7852x; 2.0744x over previous
#include <cuda_runtime.h>
#include <cuda_bf16.h>
#include <math.h>
#include <stdint.h>

// Problem constants
#define B_   4
#define S_   2048
#define D_   1024
#define H_   16
#define DK_  64
#define M_ROWS (B_ * S_)      // 8192

// ---------------------------------------------------------------------------
// Scratch (device globals; no allocation allowed)
// ---------------------------------------------------------------------------
__device__ float g_ctx[(size_t)B_ * S_ * D_];            // [B,S,D]
__device__ __nv_bfloat16 g_qh[(size_t)B_ * H_ * S_ * DK_];
__device__ __nv_bfloat16 g_ql[(size_t)B_ * H_ * S_ * DK_];
__device__ __nv_bfloat16 g_kh[(size_t)B_ * H_ * S_ * DK_];
__device__ __nv_bfloat16 g_kl[(size_t)B_ * H_ * S_ * DK_];
__device__ __nv_bfloat16 g_vh[(size_t)B_ * H_ * S_ * DK_];
__device__ __nv_bfloat16 g_vl[(size_t)B_ * H_ * S_ * DK_];
__device__ __nv_bfloat16 g_ah[(size_t)M_ROWS * D_];   // activation hi
__device__ __nv_bfloat16 g_al[(size_t)M_ROWS * D_];   // activation lo
__device__ __nv_bfloat16 g_wh[(size_t)D_ * D_];       // weight hi
__device__ __nv_bfloat16 g_wl[(size_t)D_ * D_];       // weight lo

// ---------------------------------------------------------------------------
// Helpers (baseline PTX only — NO tcgen05; harness targets plain sm_103)
// ---------------------------------------------------------------------------
__device__ __forceinline__ uint32_t smem_u32(const void* p) {
    uint32_t a;
    asm("{ .reg .u64 t; cvta.to.shared.u64 t, %1; cvt.u32.u64 %0, t; }"
        : "=r"(a) : "l"(p));
    return a;
}

__device__ __forceinline__ void cp16(uint32_t dst, const void* src) {
    asm volatile("cp.async.cg.shared.global [%0], [%1], 16;" :: "r"(dst), "l"(src));
}

__device__ __forceinline__ void ldm4(uint32_t* r, uint32_t addr) {
    asm volatile("ldmatrix.sync.aligned.m8n8.x4.shared.b16 {%0,%1,%2,%3}, [%4];"
                 : "=r"(r[0]), "=r"(r[1]), "=r"(r[2]), "=r"(r[3]) : "r"(addr));
}

__device__ __forceinline__ void ldm4t(uint32_t* r, uint32_t addr) {
    asm volatile("ldmatrix.sync.aligned.m8n8.x4.trans.shared.b16 {%0,%1,%2,%3}, [%4];"
                 : "=r"(r[0]), "=r"(r[1]), "=r"(r[2]), "=r"(r[3]) : "r"(addr));
}

__device__ __forceinline__ void mma16816(float* d, const uint32_t* a, const uint32_t* b) {
    asm volatile(
        "mma.sync.aligned.m16n8k16.row.col.f32.bf16.bf16.f32 "
        "{%0,%1,%2,%3}, {%4,%5,%6,%7}, {%8,%9}, {%0,%1,%2,%3};"
        : "+f"(d[0]), "+f"(d[1]), "+f"(d[2]), "+f"(d[3])
        : "r"(a[0]), "r"(a[1]), "r"(a[2]), "r"(a[3]), "r"(b[0]), "r"(b[1]));
}

// pack two floats into bf16x2 (lo_elem -> lower 16, hi_elem -> upper 16)
__device__ __forceinline__ uint32_t pack_bf16x2(float lo_elem, float hi_elem) {
    uint32_t r;
    asm("cvt.rn.bf16x2.f32 %0, %1, %2;" : "=r"(r) : "f"(hi_elem), "f"(lo_elem));
    return r;
}

__device__ __forceinline__ float trunc_bf(float x) {
    return __uint_as_float(__float_as_uint(x) & 0xFFFF0000u);
}

// ---------------------------------------------------------------------------
// fp32 -> (hi, lo) bf16 split (for final-GEMM inputs)
// ---------------------------------------------------------------------------
__global__ __launch_bounds__(256)
void split_bf16(const float* __restrict__ in, __nv_bfloat16* __restrict__ hi,
                __nv_bfloat16* __restrict__ lo, int n4)
{
    int i = blockIdx.x * blockDim.x + threadIdx.x;
    if (i >= n4) return;
    float4 v = ((const float4*)in)[i];
    float h0 = trunc_bf(v.x), h1 = trunc_bf(v.y), h2 = trunc_bf(v.z), h3 = trunc_bf(v.w);
    uint32_t* hp = (uint32_t*)hi;
    uint32_t* lp = (uint32_t*)lo;
    hp[2 * i]     = (__float_as_uint(v.x) >> 16) | (__float_as_uint(v.y) & 0xFFFF0000u);
    hp[2 * i + 1] = (__float_as_uint(v.z) >> 16) | (__float_as_uint(v.w) & 0xFFFF0000u);
    lp[2 * i]     = pack_bf16x2(v.x - h0, v.y - h1);
    lp[2 * i + 1] = pack_bf16x2(v.z - h2, v.w - h3);
}

// ---------------------------------------------------------------------------
// HMMA NT GEMM with hi/lo split: C[M,N] = A[M,K]*B[N,K]^T, fp32 acc
// Tile 128x128, BK=32 bf16, 256 threads = 8 warps (2x4), warp tile 64x32.
// MODE 1: scale then write bf16 hi/lo scattered into [B,H,S,dk].
// MODE 2: fp32 row-major + bias.
// ---------------------------------------------------------------------------
#define GSTRIDE 40                       // padded bf16 elems per smem row
#define MATB    (128 * GSTRIDE * 2)      // 10240 bytes per matrix
#define STAGEB  (4 * MATB)               // 40960 bytes per stage
#define GSMEM   (2 * STAGEB)             // 81920 bytes
#define NCHUNK  (D_ / 32)                // 32

template <int MODE>
__global__ __launch_bounds__(256)
void gemm_mma(const __nv_bfloat16* __restrict__ Ah, const __nv_bfloat16* __restrict__ Al,
              const __nv_bfloat16* __restrict__ Bh, const __nv_bfloat16* __restrict__ Bl,
              const float* __restrict__ bias, float* __restrict__ Cf,
              __nv_bfloat16* __restrict__ Chi, __nv_bfloat16* __restrict__ Clo,
              float scale)
{
    extern __shared__ char smc[];
    const uint32_t sb = smem_u32(smc);
    const int tid = threadIdx.x;
    const int lane = tid & 31;
    const int wid = tid >> 5;
    const int mBase = blockIdx.y * 128;
    const int nBase = blockIdx.x * 128;
    const int wm = (wid >> 2) * 64;
    const int wn = (wid & 3) * 32;

    const int lrow = tid >> 1;
    const int lch = (tid & 1) * 2;
    const __nv_bfloat16* gAh = Ah + (size_t)(mBase + lrow) * D_ + lch * 8;
    const __nv_bfloat16* gAl = Al + (size_t)(mBase + lrow) * D_ + lch * 8;
    const __nv_bfloat16* gBh = Bh + (size_t)(nBase + lrow) * D_ + lch * 8;
    const __nv_bfloat16* gBl = Bl + (size_t)(nBase + lrow) * D_ + lch * 8;
    const uint32_t dsto = (uint32_t)(lrow * (GSTRIDE * 2) + lch * 16);

    float acc[4][4][4];
#pragma unroll
    for (int mi = 0; mi < 4; ++mi)
#pragma unroll
        for (int nj = 0; nj < 4; ++nj)
#pragma unroll
            for (int e = 0; e < 4; ++e) acc[mi][nj][e] = 0.0f;

    const uint32_t a_rc = (uint32_t)((wm + (lane & 15)) * (GSTRIDE * 2) + (lane >> 4) * 16);
    const uint32_t b_rc = (uint32_t)((wn + (lane >> 4) * 8 + (lane & 7)) * (GSTRIDE * 2)
                                     + ((lane >> 3) & 1) * 16);

    {
        const uint32_t s0 = sb;
        cp16(s0 + dsto,                 gAh);
        cp16(s0 + dsto + 16,            gAh + 8);
        cp16(s0 + MATB + dsto,          gAl);
        cp16(s0 + MATB + dsto + 16,     gAl + 8);
        cp16(s0 + 2 * MATB + dsto,      gBh);
        cp16(s0 + 2 * MATB + dsto + 16, gBh + 8);
        cp16(s0 + 3 * MATB + dsto,      gBl);
        cp16(s0 + 3 * MATB + dsto + 16, gBl + 8);
        asm volatile("cp.async.commit_group;" ::: "memory");
    }

    for (int c = 0; c < NCHUNK; ++c) {
        if (c + 1 < NCHUNK) {
            const uint32_t s0 = sb + ((c + 1) & 1) * STAGEB;
            const int kb = (c + 1) * 32;
            cp16(s0 + dsto,                 gAh + kb);
            cp16(s0 + dsto + 16,            gAh + kb + 8);
            cp16(s0 + MATB + dsto,          gAl + kb);
            cp16(s0 + MATB + dsto + 16,     gAl + kb + 8);
            cp16(s0 + 2 * MATB + dsto,      gBh + kb);
            cp16(s0 + 2 * MATB + dsto + 16, gBh + kb + 8);
            cp16(s0 + 3 * MATB + dsto,      gBl + kb);
            cp16(s0 + 3 * MATB + dsto + 16, gBl + kb + 8);
            asm volatile("cp.async.commit_group;" ::: "memory");
            asm volatile("cp.async.wait_group 1;" ::: "memory");
        } else {
            asm volatile("cp.async.wait_group 0;" ::: "memory");
        }
        __syncthreads();

        const uint32_t sAh = sb + (c & 1) * STAGEB;
        const uint32_t sAl = sAh + MATB;
        const uint32_t sBh = sAh + 2 * MATB;
        const uint32_t sBl = sAh + 3 * MATB;

#pragma unroll
        for (int ks = 0; ks < 2; ++ks) {
            const uint32_t kbyte = (uint32_t)(ks * 32);
            uint32_t bh[2][4], bl[2][4];
#pragma unroll
            for (int nj = 0; nj < 2; ++nj) {
                const uint32_t boff = b_rc + kbyte + (uint32_t)(nj * 16 * GSTRIDE * 2);
                ldm4(bh[nj], sBh + boff);
                ldm4(bl[nj], sBl + boff);
            }
#pragma unroll
            for (int mi = 0; mi < 4; ++mi) {
                const uint32_t aoff = a_rc + kbyte + (uint32_t)(mi * 16 * GSTRIDE * 2);
                uint32_t ah[4], al[4];
                ldm4(ah, sAh + aoff);
                ldm4(al, sAl + aoff);
#pragma unroll
                for (int n8 = 0; n8 < 4; ++n8) {
                    const uint32_t* bhf = &bh[n8 >> 1][(n8 & 1) * 2];
                    const uint32_t* blf = &bl[n8 >> 1][(n8 & 1) * 2];
                    mma16816(acc[mi][n8], ah, bhf);
                    mma16816(acc[mi][n8], al, bhf);
                    mma16816(acc[mi][n8], ah, blf);
                }
            }
        }
        __syncthreads();
    }

    const int g = lane >> 2;
    const int i2 = (lane & 3) * 2;
#pragma unroll
    for (int mi = 0; mi < 4; ++mi) {
#pragma unroll
        for (int n8 = 0; n8 < 4; ++n8) {
            const int row0 = mBase + wm + mi * 16 + g;
            const int row1 = row0 + 8;
            const int col = nBase + wn + n8 * 8 + i2;
            float v00 = acc[mi][n8][0], v01 = acc[mi][n8][1];
            float v10 = acc[mi][n8][2], v11 = acc[mi][n8][3];
            if (MODE == 2) {
                float2 o0, o1;
                o0.x = v00 + bias[col]; o0.y = v01 + bias[col + 1];
                o1.x = v10 + bias[col]; o1.y = v11 + bias[col + 1];
                *(float2*)(Cf + (size_t)row0 * D_ + col) = o0;
                *(float2*)(Cf + (size_t)row1 * D_ + col) = o1;
            } else {
                v00 *= scale; v01 *= scale; v10 *= scale; v11 *= scale;
                const int h = col >> 6;
                const int d0 = col & 63;
                const int b0i = row0 >> 11, s0i = row0 & 2047;
                const int b1i = row1 >> 11, s1i = row1 & 2047;
                const size_t o0 = ((((size_t)(b0i * H_ + h)) * S_ + s0i) * DK_ + d0) >> 1;
                const size_t o1 = ((((size_t)(b1i * H_ + h)) * S_ + s1i) * DK_ + d0) >> 1;
                ((uint32_t*)Chi)[o0] = (__float_as_uint(v00) >> 16) | (__float_as_uint(v01) & 0xFFFF0000u);
                ((uint32_t*)Chi)[o1] = (__float_as_uint(v10) >> 16) | (__float_as_uint(v11) & 0xFFFF0000u);
                ((uint32_t*)Clo)[o0] = pack_bf16x2(v00 - trunc_bf(v00), v01 - trunc_bf(v01));
                ((uint32_t*)Clo)[o1] = pack_bf16x2(v10 - trunc_bf(v10), v11 - trunc_bf(v11));
            }
        }
    }
}

// ---------------------------------------------------------------------------
// HMMA flash attention. CTA: 128 queries x (loop over 16 key-tiles of 128).
// 8 warps, warp = 16 q-rows. K/V hi/lo double-buffered cp.async.
// Q pre-scaled by 1/sqrt(dk) at projection time. hi/lo 3-pass MMAs.
// ---------------------------------------------------------------------------
#define ASTB  144                       // 72 bf16 per row (64 + pad 8)
#define AMATB (128 * ASTB)              // 18432 bytes
#define ATT_SMEM2 (10 * AMATB)          // Qh,Ql + 2 stages x (Kh,Kl,Vh,Vl) = 184320

__global__ __launch_bounds__(256)
void attn_mma(const __nv_bfloat16* __restrict__ Qh, const __nv_bfloat16* __restrict__ Ql,
              const __nv_bfloat16* __restrict__ Kh, const __nv_bfloat16* __restrict__ Kl,
              const __nv_bfloat16* __restrict__ Vh, const __nv_bfloat16* __restrict__ Vl,
              float* __restrict__ ctx)
{
    extern __shared__ char smc[];
    const uint32_t sb = smem_u32(smc);
    const int tid = threadIdx.x;
    const int lane = tid & 31;
    const int wid = tid >> 5;
    const int bh = blockIdx.y;          // 0..63
    const int qt = blockIdx.x;          // 0..15

    const uint32_t sQh = sb;
    const uint32_t sQl = sb + AMATB;

    // tile bases in gmem
    const size_t qoff = ((size_t)bh * S_ + qt * 128) * DK_;
    const size_t kvoff = (size_t)bh * S_ * DK_;

    // loader: 4 x (row, 16B-chunk) tasks per thread per matrix
    const int t0 = tid;

    // Q + stage 0
    {
#pragma unroll
        for (int j = 0; j < 4; ++j) {
            int task = t0 + 256 * j;
            int row = task >> 3, ch = task & 7;
            uint32_t so = (uint32_t)(row * ASTB + ch * 16);
            cp16(sQh + so, Qh + qoff + (size_t)row * DK_ + ch * 8);
            cp16(sQl + so, Ql + qoff + (size_t)row * DK_ + ch * 8);
            const uint32_t st = sb + 2 * AMATB;     // stage 0
            cp16(st + so,             Kh + kvoff + (size_t)row * DK_ + ch * 8);
            cp16(st + AMATB + so,     Kl + kvoff + (size_t)row * DK_ + ch * 8);
            cp16(st + 2 * AMATB + so, Vh + kvoff + (size_t)row * DK_ + ch * 8);
            cp16(st + 3 * AMATB + so, Vl + kvoff + (size_t)row * DK_ + ch * 8);
        }
        asm volatile("cp.async.commit_group;" ::: "memory");
    }

    uint32_t qfh[4][4], qfl[4][4];
    float o[8][4];
#pragma unroll
    for (int f = 0; f < 8; ++f)
#pragma unroll
        for (int e = 0; e < 4; ++e) o[f][e] = 0.0f;
    float mrow[2] = {-INFINITY, -INFINITY};
    float lrow[2] = {0.0f, 0.0f};

    const uint32_t a_rc = (uint32_t)((wid * 16 + (lane & 15)) * ASTB + (lane >> 4) * 16);
    const uint32_t b_rc = (uint32_t)(((lane >> 4) * 8 + (lane & 7)) * ASTB
                                     + ((lane >> 3) & 1) * 16);

    for (int kt = 0; kt < 16; ++kt) {
        if (kt + 1 < 16) {
            const uint32_t st = sb + 2 * AMATB + ((kt + 1) & 1) * 4 * AMATB;
            const size_t base = kvoff + (size_t)(kt + 1) * 128 * DK_;
#pragma unroll
            for (int j = 0; j < 4; ++j) {
                int task = t0 + 256 * j;
                int row = task >> 3, ch = task & 7;
                uint32_t so = (uint32_t)(row * ASTB + ch * 16);
                cp16(st + so,             Kh + base + (size_t)row * DK_ + ch * 8);
                cp16(st + AMATB + so,     Kl + base + (size_t)row * DK_ + ch * 8);
                cp16(st + 2 * AMATB + so, Vh + base + (size_t)row * DK_ + ch * 8);
                cp16(st + 3 * AMATB + so, Vl + base + (size_t)row * DK_ + ch * 8);
            }
            asm volatile("cp.async.commit_group;" ::: "memory");
            asm volatile("cp.async.wait_group 1;" ::: "memory");
        } else {
            asm volatile("cp.async.wait_group 0;" ::: "memory");
        }
        __syncthreads();

        if (kt == 0) {
            // load Q fragments once
#pragma unroll
            for (int kc = 0; kc < 4; ++kc) {
                ldm4(qfh[kc], sQh + a_rc + kc * 32);
                ldm4(qfl[kc], sQl + a_rc + kc * 32);
            }
        }

        const uint32_t st = sb + 2 * AMATB + (kt & 1) * 4 * AMATB;
        const uint32_t sKh = st;
        const uint32_t sKl = st + AMATB;
        const uint32_t sVh = st + 2 * AMATB;
        const uint32_t sVl = st + 3 * AMATB;

        // ---- S = Q K^T : 16 n8 frags of 128 keys ----
        float sc[16][4];
#pragma unroll
        for (int f = 0; f < 16; ++f)
#pragma unroll
            for (int e = 0; e < 4; ++e) sc[f][e] = 0.0f;

#pragma unroll
        for (int kc = 0; kc < 4; ++kc) {
#pragma unroll
            for (int n16 = 0; n16 < 8; ++n16) {
                const uint32_t boff = b_rc + (uint32_t)(n16 * 16 * ASTB) + kc * 32;
                uint32_t kh4[4], kl4[4];
                ldm4(kh4, sKh + boff);
                ldm4(kl4, sKl + boff);
                mma16816(sc[2 * n16],     qfh[kc], kh4);
                mma16816(sc[2 * n16],     qfl[kc], kh4);
                mma16816(sc[2 * n16],     qfh[kc], kl4);
                mma16816(sc[2 * n16 + 1], qfh[kc], kh4 + 2);
                mma16816(sc[2 * n16 + 1], qfl[kc], kh4 + 2);
                mma16816(sc[2 * n16 + 1], qfh[kc], kl4 + 2);
            }
        }

        // ---- online softmax (rows g and g+8) ----
#pragma unroll
        for (int r = 0; r < 2; ++r) {
            const int e0 = r * 2, e1 = r * 2 + 1;
            float rmax = -INFINITY;
#pragma unroll
            for (int f = 0; f < 16; ++f)
                rmax = fmaxf(rmax, fmaxf(sc[f][e0], sc[f][e1]));
            rmax = fmaxf(rmax, __shfl_xor_sync(0xffffffffu, rmax, 1));
            rmax = fmaxf(rmax, __shfl_xor_sync(0xffffffffu, rmax, 2));
            const float mnew = fmaxf(mrow[r], rmax);
            const float corr = __expf(mrow[r] - mnew);
            float rsum = 0.0f;
#pragma unroll
            for (int f = 0; f < 16; ++f) {
                float p0 = __expf(sc[f][e0] - mnew);
                float p1 = __expf(sc[f][e1] - mnew);
                sc[f][e0] = p0; sc[f][e1] = p1;
                rsum += p0 + p1;
            }
            rsum += __shfl_xor_sync(0xffffffffu, rsum, 1);
            rsum += __shfl_xor_sync(0xffffffffu, rsum, 2);
            lrow[r] = lrow[r] * corr + rsum;
            mrow[r] = mnew;
#pragma unroll
            for (int f = 0; f < 8; ++f) {
                o[f][e0] *= corr;
                o[f][e1] *= corr;
            }
        }

        // ---- pack P into bf16 hi/lo a-frags (in place over sc) ----
        uint32_t* pp = (uint32_t*)&sc[0][0];
#pragma unroll
        for (int kk = 0; kk < 8; ++kk) {
            float p00 = sc[2 * kk][0],     p01 = sc[2 * kk][1];
            float p02 = sc[2 * kk][2],     p03 = sc[2 * kk][3];
            float p10 = sc[2 * kk + 1][0], p11 = sc[2 * kk + 1][1];
            float p12 = sc[2 * kk + 1][2], p13 = sc[2 * kk + 1][3];
            uint32_t h0 = (__float_as_uint(p00) >> 16) | (__float_as_uint(p01) & 0xFFFF0000u);
            uint32_t h1 = (__float_as_uint(p02) >> 16) | (__float_as_uint(p03) & 0xFFFF0000u);
            uint32_t h2 = (__float_as_uint(p10) >> 16) | (__float_as_uint(p11) & 0xFFFF0000u);
            uint32_t h3 = (__float_as_uint(p12) >> 16) | (__float_as_uint(p13) & 0xFFFF0000u);
            uint32_t l0 = pack_bf16x2(p00 - trunc_bf(p00), p01 - trunc_bf(p01));
            uint32_t l1 = pack_bf16x2(p02 - trunc_bf(p02), p03 - trunc_bf(p03));
            uint32_t l2 = pack_bf16x2(p10 - trunc_bf(p10), p11 - trunc_bf(p11));
            uint32_t l3 = pack_bf16x2(p12 - trunc_bf(p12), p13 - trunc_bf(p13));
            pp[kk * 8 + 0] = h0; pp[kk * 8 + 1] = h1;
            pp[kk * 8 + 2] = h2; pp[kk * 8 + 3] = h3;
            pp[kk * 8 + 4] = l0; pp[kk * 8 + 5] = l1;
            pp[kk * 8 + 6] = l2; pp[kk * 8 + 7] = l3;
        }

        // ---- O += P V : k = 128 keys (8 chunks), n = 64 dk (4 n16) ----
#pragma unroll
        for (int kk = 0; kk < 8; ++kk) {
            const uint32_t* aPh = &pp[kk * 8];
            const uint32_t* aPl = &pp[kk * 8 + 4];
#pragma unroll
            for (int n16 = 0; n16 < 4; ++n16) {
                const uint32_t voff = (uint32_t)((kk * 16 + (lane & 15)) * ASTB
                                     + (n16 * 16 + (lane >> 4) * 8) * 2);
                uint32_t vh4[4], vl4[4];
                ldm4t(vh4, sVh + voff);
                ldm4t(vl4, sVl + voff);
                mma16816(o[2 * n16],     aPh, vh4);
                mma16816(o[2 * n16],     aPl, vh4);
                mma16816(o[2 * n16],     aPh, vl4);
                mma16816(o[2 * n16 + 1], aPh, vh4 + 2);
                mma16816(o[2 * n16 + 1], aPl, vh4 + 2);
                mma16816(o[2 * n16 + 1], aPh, vl4 + 2);
            }
        }
        __syncthreads();
    }

    // ---- epilogue: normalize and write ctx [B,S,H,dk] ----
    const int bb = bh >> 4;
    const int h = bh & 15;
    const int g = lane >> 2;
    const int i2 = (lane & 3) * 2;
    const int s0 = qt * 128 + wid * 16 + g;
    const int s1 = s0 + 8;
    const float inv0 = 1.0f / lrow[0];
    const float inv1 = 1.0f / lrow[1];
#pragma unroll
    for (int f = 0; f < 8; ++f) {
        const int d = f * 8 + i2;
        float2 w0, w1;
        w0.x = o[f][0] * inv0; w0.y = o[f][1] * inv0;
        w1.x = o[f][2] * inv1; w1.y = o[f][3] * inv1;
        *(float2*)(ctx + (((size_t)bb * S_ + s0) * H_ + h) * DK_ + d) = w0;
        *(float2*)(ctx + (((size_t)bb * S_ + s1) * H_ + h) * DK_ + d) = w1;
    }
}

// ---------------------------------------------------------------------------
// Launcher
// ---------------------------------------------------------------------------
extern "C" void kernel_launch(void* const* d_in, const int* in_sizes, int n_in,
                              void* d_out, int out_size)
{
    const float* query = (const float*)d_in[0];
    const float* key_  = (const float*)d_in[1];
    const float* value = (const float*)d_in[2];
    const float* w_q   = (const float*)d_in[3];
    const float* w_k   = (const float*)d_in[4];
    const float* w_v   = (const float*)d_in[5];
    const float* w_o   = (const float*)d_in[6];
    const float* b_o   = (const float*)d_in[7];
    float* out = (float*)d_out;

    float *gctx;
    __nv_bfloat16 *qh, *ql, *kh, *kl, *vh, *vl, *ah, *al, *wh, *wl;
    cudaGetSymbolAddress((void**)&gctx, g_ctx);
    cudaGetSymbolAddress((void**)&qh, g_qh);
    cudaGetSymbolAddress((void**)&ql, g_ql);
    cudaGetSymbolAddress((void**)&kh, g_kh);
    cudaGetSymbolAddress((void**)&kl, g_kl);
    cudaGetSymbolAddress((void**)&vh, g_vh);
    cudaGetSymbolAddress((void**)&vl, g_vl);
    cudaGetSymbolAddress((void**)&ah, g_ah);
    cudaGetSymbolAddress((void**)&al, g_al);
    cudaGetSymbolAddress((void**)&wh, g_wh);
    cudaGetSymbolAddress((void**)&wl, g_wl);

    cudaFuncSetAttribute(gemm_mma<1>, cudaFuncAttributeMaxDynamicSharedMemorySize, GSMEM);
    cudaFuncSetAttribute(gemm_mma<2>, cudaFuncAttributeMaxDynamicSharedMemorySize, GSMEM);
    cudaFuncSetAttribute(attn_mma, cudaFuncAttributeMaxDynamicSharedMemorySize, ATT_SMEM2);

    const int actN4 = (M_ROWS * D_) / 4;
    const int wN4   = (D_ * D_) / 4;
    dim3 gGemm(D_ / 128, M_ROWS / 128);    // (8, 64)
    const float qscale = 0.125f;           // 1/sqrt(64)

    // Q projection (pre-scaled)
    split_bf16<<<(actN4 + 255) / 256, 256>>>(query, ah, al, actN4);
    split_bf16<<<(wN4 + 255) / 256, 256>>>(w_q, wh, wl, wN4);
    gemm_mma<1><<<gGemm, 256, GSMEM>>>(ah, al, wh, wl, nullptr, nullptr, qh, ql, qscale);

    // K projection
    split_bf16<<<(actN4 + 255) / 256, 256>>>(key_, ah, al, actN4);
    split_bf16<<<(wN4 + 255) / 256, 256>>>(w_k, wh, wl, wN4);
    gemm_mma<1><<<gGemm, 256, GSMEM>>>(ah, al, wh, wl, nullptr, nullptr, kh, kl, 1.0f);

    // V projection
    split_bf16<<<(actN4 + 255) / 256, 256>>>(value, ah, al, actN4);
    split_bf16<<<(wN4 + 255) / 256, 256>>>(w_v, wh, wl, wN4);
    gemm_mma<1><<<gGemm, 256, GSMEM>>>(ah, al, wh, wl, nullptr, nullptr, vh, vl, 1.0f);

    // Attention (HMMA flash)
    dim3 gAtt(S_ / 128, B_ * H_);          // (16, 64)
    attn_mma<<<gAtt, 256, ATT_SMEM2>>>(qh, ql, kh, kl, vh, vl, gctx);

    // Output projection + bias
    split_bf16<<<(actN4 + 255) / 256, 256>>>(gctx, ah, al, actN4);
    split_bf16<<<(wN4 + 255) / 256, 256>>>(w_o, wh, wl, wN4);
    gemm_mma<2><<<gGemm, 256, GSMEM>>>(ah, al, wh, wl, b_o, out, nullptr, nullptr, 1.0f);
}

// round 11
// speedup vs baseline: 3.8467x; 1.3811x over previous
#include <cuda_runtime.h>
#include <cuda_fp16.h>
#include <math.h>
#include <stdint.h>

// Problem constants
#define B_   4
#define S_   2048
#define D_   1024
#define H_   16
#define DK_  64
#define M_ROWS (B_ * S_)      // 8192

// ---------------------------------------------------------------------------
// Scratch (device globals; no allocation allowed)
// ---------------------------------------------------------------------------
__device__ float g_ctx[(size_t)B_ * S_ * D_];            // [B,S,D]
__device__ __half g_qh[(size_t)B_ * H_ * S_ * DK_];
__device__ __half g_ql[(size_t)B_ * H_ * S_ * DK_];
__device__ __half g_kh[(size_t)B_ * H_ * S_ * DK_];
__device__ __half g_vh[(size_t)B_ * H_ * S_ * DK_];
__device__ __half g_ah[(size_t)M_ROWS * D_];   // activation hi
__device__ __half g_al[(size_t)M_ROWS * D_];   // activation lo
__device__ __half g_wh[(size_t)D_ * D_];       // weight hi (lo not needed)

// ---------------------------------------------------------------------------
// Helpers (baseline PTX only — NO tcgen05; harness targets plain sm_103)
// ---------------------------------------------------------------------------
__device__ __forceinline__ uint32_t smem_u32(const void* p) {
    uint32_t a;
    asm("{ .reg .u64 t; cvta.to.shared.u64 t, %1; cvt.u32.u64 %0, t; }"
        : "=r"(a) : "l"(p));
    return a;
}

__device__ __forceinline__ void cp16(uint32_t dst, const void* src) {
    asm volatile("cp.async.cg.shared.global [%0], [%1], 16;" :: "r"(dst), "l"(src));
}

__device__ __forceinline__ void ldm4(uint32_t* r, uint32_t addr) {
    asm volatile("ldmatrix.sync.aligned.m8n8.x4.shared.b16 {%0,%1,%2,%3}, [%4];"
                 : "=r"(r[0]), "=r"(r[1]), "=r"(r[2]), "=r"(r[3]) : "r"(addr));
}

__device__ __forceinline__ void ldm4t(uint32_t* r, uint32_t addr) {
    asm volatile("ldmatrix.sync.aligned.m8n8.x4.trans.shared.b16 {%0,%1,%2,%3}, [%4];"
                 : "=r"(r[0]), "=r"(r[1]), "=r"(r[2]), "=r"(r[3]) : "r"(addr));
}

__device__ __forceinline__ void mma16816(float* d, const uint32_t* a, const uint32_t* b) {
    asm volatile(
        "mma.sync.aligned.m16n8k16.row.col.f32.f16.f16.f32 "
        "{%0,%1,%2,%3}, {%4,%5,%6,%7}, {%8,%9}, {%0,%1,%2,%3};"
        : "+f"(d[0]), "+f"(d[1]), "+f"(d[2]), "+f"(d[3])
        : "r"(a[0]), "r"(a[1]), "r"(a[2]), "r"(a[3]), "r"(b[0]), "r"(b[1]));
}

// pack two floats -> f16x2 (a -> low 16, b -> high 16) and return both halves as f32
__device__ __forceinline__ uint32_t pack_f16x2(float a, float b) {
    __half2 h = __floats2half2_rn(a, b);
    return *(uint32_t*)&h;
}

__device__ __forceinline__ void split2_f16(float a, float b, uint32_t& hi, uint32_t& lo) {
    __half2 h = __floats2half2_rn(a, b);
    float fa = __low2float(h), fb = __high2float(h);
    __half2 l = __floats2half2_rn(a - fa, b - fb);
    hi = *(uint32_t*)&h;
    lo = *(uint32_t*)&l;
}

// ---------------------------------------------------------------------------
// fp32 -> (hi, lo) fp16 split ; and hi-only variant (weights)
// ---------------------------------------------------------------------------
__global__ __launch_bounds__(256)
void split_f16(const float* __restrict__ in, __half* __restrict__ hi,
               __half* __restrict__ lo, int n4)
{
    int i = blockIdx.x * blockDim.x + threadIdx.x;
    if (i >= n4) return;
    float4 v = ((const float4*)in)[i];
    uint32_t h0, l0, h1, l1;
    split2_f16(v.x, v.y, h0, l0);
    split2_f16(v.z, v.w, h1, l1);
    ((uint32_t*)hi)[2 * i] = h0;
    ((uint32_t*)hi)[2 * i + 1] = h1;
    ((uint32_t*)lo)[2 * i] = l0;
    ((uint32_t*)lo)[2 * i + 1] = l1;
}

__global__ __launch_bounds__(256)
void split_f16_hi(const float* __restrict__ in, __half* __restrict__ hi, int n4)
{
    int i = blockIdx.x * blockDim.x + threadIdx.x;
    if (i >= n4) return;
    float4 v = ((const float4*)in)[i];
    ((uint32_t*)hi)[2 * i]     = pack_f16x2(v.x, v.y);
    ((uint32_t*)hi)[2 * i + 1] = pack_f16x2(v.z, v.w);
}

// ---------------------------------------------------------------------------
// HMMA NT GEMM, fp16 2-pass (A hi/lo, B hi-only): C = (Ah+Al) * Bh^T, fp32 acc
// Tile 128x128, BK=32, 256 threads = 8 warps (2x4), warp tile 64x32.
// MODE 1: scale then write fp16 hi(/lo) scattered into [B,H,S,dk].
// MODE 2: fp32 row-major + bias.
// ---------------------------------------------------------------------------
#define GSTRIDE 40                       // padded fp16 elems per smem row
#define MATB    (128 * GSTRIDE * 2)      // 10240 bytes per matrix
#define STAGEB  (3 * MATB)               // 30720 bytes per stage (Ah, Al, Bh)
#define GSMEM   (2 * STAGEB)             // 61440 bytes
#define NCHUNK  (D_ / 32)                // 32

template <int MODE>
__global__ __launch_bounds__(256)
void gemm_mma(const __half* __restrict__ Ah, const __half* __restrict__ Al,
              const __half* __restrict__ Bh,
              const float* __restrict__ bias, float* __restrict__ Cf,
              __half* __restrict__ Chi, __half* __restrict__ Clo,
              float scale)
{
    extern __shared__ char smc[];
    const uint32_t sb = smem_u32(smc);
    const int tid = threadIdx.x;
    const int lane = tid & 31;
    const int wid = tid >> 5;
    const int mBase = blockIdx.y * 128;
    const int nBase = blockIdx.x * 128;
    const int wm = (wid >> 2) * 64;
    const int wn = (wid & 3) * 32;

    const int lrow = tid >> 1;
    const int lch = (tid & 1) * 2;
    const __half* gAh = Ah + (size_t)(mBase + lrow) * D_ + lch * 8;
    const __half* gAl = Al + (size_t)(mBase + lrow) * D_ + lch * 8;
    const __half* gBh = Bh + (size_t)(nBase + lrow) * D_ + lch * 8;
    const uint32_t dsto = (uint32_t)(lrow * (GSTRIDE * 2) + lch * 16);

    float acc[4][4][4];
#pragma unroll
    for (int mi = 0; mi < 4; ++mi)
#pragma unroll
        for (int nj = 0; nj < 4; ++nj)
#pragma unroll
            for (int e = 0; e < 4; ++e) acc[mi][nj][e] = 0.0f;

    const uint32_t a_rc = (uint32_t)((wm + (lane & 15)) * (GSTRIDE * 2) + (lane >> 4) * 16);
    const uint32_t b_rc = (uint32_t)((wn + (lane >> 4) * 8 + (lane & 7)) * (GSTRIDE * 2)
                                     + ((lane >> 3) & 1) * 16);

    {
        const uint32_t s0 = sb;
        cp16(s0 + dsto,                 gAh);
        cp16(s0 + dsto + 16,            gAh + 8);
        cp16(s0 + MATB + dsto,          gAl);
        cp16(s0 + MATB + dsto + 16,     gAl + 8);
        cp16(s0 + 2 * MATB + dsto,      gBh);
        cp16(s0 + 2 * MATB + dsto + 16, gBh + 8);
        asm volatile("cp.async.commit_group;" ::: "memory");
    }

    for (int c = 0; c < NCHUNK; ++c) {
        if (c + 1 < NCHUNK) {
            const uint32_t s0 = sb + ((c + 1) & 1) * STAGEB;
            const int kb = (c + 1) * 32;
            cp16(s0 + dsto,                 gAh + kb);
            cp16(s0 + dsto + 16,            gAh + kb + 8);
            cp16(s0 + MATB + dsto,          gAl + kb);
            cp16(s0 + MATB + dsto + 16,     gAl + kb + 8);
            cp16(s0 + 2 * MATB + dsto,      gBh + kb);
            cp16(s0 + 2 * MATB + dsto + 16, gBh + kb + 8);
            asm volatile("cp.async.commit_group;" ::: "memory");
            asm volatile("cp.async.wait_group 1;" ::: "memory");
        } else {
            asm volatile("cp.async.wait_group 0;" ::: "memory");
        }
        __syncthreads();

        const uint32_t sAh = sb + (c & 1) * STAGEB;
        const uint32_t sAl = sAh + MATB;
        const uint32_t sBh = sAh + 2 * MATB;

#pragma unroll
        for (int ks = 0; ks < 2; ++ks) {
            const uint32_t kbyte = (uint32_t)(ks * 32);
            uint32_t bh[2][4];
#pragma unroll
            for (int nj = 0; nj < 2; ++nj) {
                const uint32_t boff = b_rc + kbyte + (uint32_t)(nj * 16 * GSTRIDE * 2);
                ldm4(bh[nj], sBh + boff);
            }
#pragma unroll
            for (int mi = 0; mi < 4; ++mi) {
                const uint32_t aoff = a_rc + kbyte + (uint32_t)(mi * 16 * GSTRIDE * 2);
                uint32_t ah[4], al[4];
                ldm4(ah, sAh + aoff);
                ldm4(al, sAl + aoff);
#pragma unroll
                for (int n8 = 0; n8 < 4; ++n8) {
                    const uint32_t* bhf = &bh[n8 >> 1][(n8 & 1) * 2];
                    mma16816(acc[mi][n8], ah, bhf);
                    mma16816(acc[mi][n8], al, bhf);
                }
            }
        }
        __syncthreads();
    }

    const int g = lane >> 2;
    const int i2 = (lane & 3) * 2;
#pragma unroll
    for (int mi = 0; mi < 4; ++mi) {
#pragma unroll
        for (int n8 = 0; n8 < 4; ++n8) {
            const int row0 = mBase + wm + mi * 16 + g;
            const int row1 = row0 + 8;
            const int col = nBase + wn + n8 * 8 + i2;
            float v00 = acc[mi][n8][0], v01 = acc[mi][n8][1];
            float v10 = acc[mi][n8][2], v11 = acc[mi][n8][3];
            if (MODE == 2) {
                float2 o0, o1;
                o0.x = v00 + bias[col]; o0.y = v01 + bias[col + 1];
                o1.x = v10 + bias[col]; o1.y = v11 + bias[col + 1];
                *(float2*)(Cf + (size_t)row0 * D_ + col) = o0;
                *(float2*)(Cf + (size_t)row1 * D_ + col) = o1;
            } else {
                v00 *= scale; v01 *= scale; v10 *= scale; v11 *= scale;
                const int h = col >> 6;
                const int d0 = col & 63;
                const int b0i = row0 >> 11, s0i = row0 & 2047;
                const int b1i = row1 >> 11, s1i = row1 & 2047;
                const size_t o0 = ((((size_t)(b0i * H_ + h)) * S_ + s0i) * DK_ + d0) >> 1;
                const size_t o1 = ((((size_t)(b1i * H_ + h)) * S_ + s1i) * DK_ + d0) >> 1;
                if (Clo) {
                    uint32_t h0, l0, h1, l1;
                    split2_f16(v00, v01, h0, l0);
                    split2_f16(v10, v11, h1, l1);
                    ((uint32_t*)Chi)[o0] = h0;
                    ((uint32_t*)Chi)[o1] = h1;
                    ((uint32_t*)Clo)[o0] = l0;
                    ((uint32_t*)Clo)[o1] = l1;
                } else {
                    ((uint32_t*)Chi)[o0] = pack_f16x2(v00, v01);
                    ((uint32_t*)Chi)[o1] = pack_f16x2(v10, v11);
                }
            }
        }
    }
}

// ---------------------------------------------------------------------------
// HMMA flash attention, fp16. Q 2-pass (hi/lo), K/V plain fp16, P 2-pass.
// CTA: 128 queries x (loop over 16 key-tiles of 128). 8 warps.
// ---------------------------------------------------------------------------
#define ASTB  144                       // bytes per smem row (64+8 fp16)
#define AMATB (128 * ASTB)              // 18432 bytes
#define ATT_SMEM2 (6 * AMATB)           // Qh,Ql + 2 stages x (Kh,Vh) = 110592

__global__ __launch_bounds__(256)
void attn_mma(const __half* __restrict__ Qh, const __half* __restrict__ Ql,
              const __half* __restrict__ Kh, const __half* __restrict__ Vh,
              float* __restrict__ ctx)
{
    extern __shared__ char smc[];
    const uint32_t sb = smem_u32(smc);
    const int tid = threadIdx.x;
    const int lane = tid & 31;
    const int wid = tid >> 5;
    const int bh = blockIdx.y;          // 0..63
    const int qt = blockIdx.x;          // 0..15

    const uint32_t sQh = sb;
    const uint32_t sQl = sb + AMATB;

    const size_t qoff = ((size_t)bh * S_ + qt * 128) * DK_;
    const size_t kvoff = (size_t)bh * S_ * DK_;

    // Q + stage 0
    {
#pragma unroll
        for (int j = 0; j < 4; ++j) {
            int task = tid + 256 * j;
            int row = task >> 3, ch = task & 7;
            uint32_t so = (uint32_t)(row * ASTB + ch * 16);
            cp16(sQh + so, Qh + qoff + (size_t)row * DK_ + ch * 8);
            cp16(sQl + so, Ql + qoff + (size_t)row * DK_ + ch * 8);
            const uint32_t st = sb + 2 * AMATB;     // stage 0
            cp16(st + so,         Kh + kvoff + (size_t)row * DK_ + ch * 8);
            cp16(st + AMATB + so, Vh + kvoff + (size_t)row * DK_ + ch * 8);
        }
        asm volatile("cp.async.commit_group;" ::: "memory");
    }

    uint32_t qfh[4][4], qfl[4][4];
    float o[8][4];
#pragma unroll
    for (int f = 0; f < 8; ++f)
#pragma unroll
        for (int e = 0; e < 4; ++e) o[f][e] = 0.0f;
    float mrow[2] = {-INFINITY, -INFINITY};
    float lrow[2] = {0.0f, 0.0f};

    const uint32_t a_rc = (uint32_t)((wid * 16 + (lane & 15)) * ASTB + (lane >> 4) * 16);
    const uint32_t b_rc = (uint32_t)(((lane >> 4) * 8 + (lane & 7)) * ASTB
                                     + ((lane >> 3) & 1) * 16);

    for (int kt = 0; kt < 16; ++kt) {
        if (kt + 1 < 16) {
            const uint32_t st = sb + 2 * AMATB + ((kt + 1) & 1) * 2 * AMATB;
            const size_t base = kvoff + (size_t)(kt + 1) * 128 * DK_;
#pragma unroll
            for (int j = 0; j < 4; ++j) {
                int task = tid + 256 * j;
                int row = task >> 3, ch = task & 7;
                uint32_t so = (uint32_t)(row * ASTB + ch * 16);
                cp16(st + so,         Kh + base + (size_t)row * DK_ + ch * 8);
                cp16(st + AMATB + so, Vh + base + (size_t)row * DK_ + ch * 8);
            }
            asm volatile("cp.async.commit_group;" ::: "memory");
            asm volatile("cp.async.wait_group 1;" ::: "memory");
        } else {
            asm volatile("cp.async.wait_group 0;" ::: "memory");
        }
        __syncthreads();

        if (kt == 0) {
#pragma unroll
            for (int kc = 0; kc < 4; ++kc) {
                ldm4(qfh[kc], sQh + a_rc + kc * 32);
                ldm4(qfl[kc], sQl + a_rc + kc * 32);
            }
        }

        const uint32_t st = sb + 2 * AMATB + (kt & 1) * 2 * AMATB;
        const uint32_t sKh = st;
        const uint32_t sVh = st + AMATB;

        // ---- S = Q K^T ----
        float sc[16][4];
#pragma unroll
        for (int f = 0; f < 16; ++f)
#pragma unroll
            for (int e = 0; e < 4; ++e) sc[f][e] = 0.0f;

#pragma unroll
        for (int kc = 0; kc < 4; ++kc) {
#pragma unroll
            for (int n16 = 0; n16 < 8; ++n16) {
                const uint32_t boff = b_rc + (uint32_t)(n16 * 16 * ASTB) + kc * 32;
                uint32_t kh4[4];
                ldm4(kh4, sKh + boff);
                mma16816(sc[2 * n16],     qfh[kc], kh4);
                mma16816(sc[2 * n16],     qfl[kc], kh4);
                mma16816(sc[2 * n16 + 1], qfh[kc], kh4 + 2);
                mma16816(sc[2 * n16 + 1], qfl[kc], kh4 + 2);
            }
        }

        // ---- online softmax (rows g and g+8) ----
#pragma unroll
        for (int r = 0; r < 2; ++r) {
            const int e0 = r * 2, e1 = r * 2 + 1;
            float rmax = -INFINITY;
#pragma unroll
            for (int f = 0; f < 16; ++f)
                rmax = fmaxf(rmax, fmaxf(sc[f][e0], sc[f][e1]));
            rmax = fmaxf(rmax, __shfl_xor_sync(0xffffffffu, rmax, 1));
            rmax = fmaxf(rmax, __shfl_xor_sync(0xffffffffu, rmax, 2));
            const float mnew = fmaxf(mrow[r], rmax);
            const float corr = __expf(mrow[r] - mnew);
            float rsum = 0.0f;
#pragma unroll
            for (int f = 0; f < 16; ++f) {
                float p0 = __expf(sc[f][e0] - mnew);
                float p1 = __expf(sc[f][e1] - mnew);
                sc[f][e0] = p0; sc[f][e1] = p1;
                rsum += p0 + p1;
            }
            rsum += __shfl_xor_sync(0xffffffffu, rsum, 1);
            rsum += __shfl_xor_sync(0xffffffffu, rsum, 2);
            lrow[r] = lrow[r] * corr + rsum;
            mrow[r] = mnew;
#pragma unroll
            for (int f = 0; f < 8; ++f) {
                o[f][e0] *= corr;
                o[f][e1] *= corr;
            }
        }

        // ---- pack P into fp16 hi/lo a-frags (in place over sc) ----
        uint32_t* pp = (uint32_t*)&sc[0][0];
#pragma unroll
        for (int kk = 0; kk < 8; ++kk) {
            float p00 = sc[2 * kk][0],     p01 = sc[2 * kk][1];
            float p02 = sc[2 * kk][2],     p03 = sc[2 * kk][3];
            float p10 = sc[2 * kk + 1][0], p11 = sc[2 * kk + 1][1];
            float p12 = sc[2 * kk + 1][2], p13 = sc[2 * kk + 1][3];
            uint32_t h0, l0, h1, l1, h2, l2, h3, l3;
            split2_f16(p00, p01, h0, l0);
            split2_f16(p02, p03, h1, l1);
            split2_f16(p10, p11, h2, l2);
            split2_f16(p12, p13, h3, l3);
            pp[kk * 8 + 0] = h0; pp[kk * 8 + 1] = h1;
            pp[kk * 8 + 2] = h2; pp[kk * 8 + 3] = h3;
            pp[kk * 8 + 4] = l0; pp[kk * 8 + 5] = l1;
            pp[kk * 8 + 6] = l2; pp[kk * 8 + 7] = l3;
        }

        // ---- O += P V ----
#pragma unroll
        for (int kk = 0; kk < 8; ++kk) {
            const uint32_t* aPh = &pp[kk * 8];
            const uint32_t* aPl = &pp[kk * 8 + 4];
#pragma unroll
            for (int n16 = 0; n16 < 4; ++n16) {
                const uint32_t voff = (uint32_t)((kk * 16 + (lane & 15)) * ASTB
                                     + (n16 * 16 + (lane >> 4) * 8) * 2);
                uint32_t vh4[4];
                ldm4t(vh4, sVh + voff);
                mma16816(o[2 * n16],     aPh, vh4);
                mma16816(o[2 * n16],     aPl, vh4);
                mma16816(o[2 * n16 + 1], aPh, vh4 + 2);
                mma16816(o[2 * n16 + 1], aPl, vh4 + 2);
            }
        }
        __syncthreads();
    }

    // ---- epilogue: normalize and write ctx [B,S,H,dk] ----
    const int bb = bh >> 4;
    const int h = bh & 15;
    const int g = lane >> 2;
    const int i2 = (lane & 3) * 2;
    const int s0 = qt * 128 + wid * 16 + g;
    const int s1 = s0 + 8;
    const float inv0 = 1.0f / lrow[0];
    const float inv1 = 1.0f / lrow[1];
#pragma unroll
    for (int f = 0; f < 8; ++f) {
        const int d = f * 8 + i2;
        float2 w0, w1;
        w0.x = o[f][0] * inv0; w0.y = o[f][1] * inv0;
        w1.x = o[f][2] * inv1; w1.y = o[f][3] * inv1;
        *(float2*)(ctx + (((size_t)bb * S_ + s0) * H_ + h) * DK_ + d) = w0;
        *(float2*)(ctx + (((size_t)bb * S_ + s1) * H_ + h) * DK_ + d) = w1;
    }
}

// ---------------------------------------------------------------------------
// Launcher
// ---------------------------------------------------------------------------
extern "C" void kernel_launch(void* const* d_in, const int* in_sizes, int n_in,
                              void* d_out, int out_size)
{
    const float* query = (const float*)d_in[0];
    const float* key_  = (const float*)d_in[1];
    const float* value = (const float*)d_in[2];
    const float* w_q   = (const float*)d_in[3];
    const float* w_k   = (const float*)d_in[4];
    const float* w_v   = (const float*)d_in[5];
    const float* w_o   = (const float*)d_in[6];
    const float* b_o   = (const float*)d_in[7];
    float* out = (float*)d_out;

    float* gctx;
    __half *qh, *ql, *kh, *vh, *ah, *al, *wh;
    cudaGetSymbolAddress((void**)&gctx, g_ctx);
    cudaGetSymbolAddress((void**)&qh, g_qh);
    cudaGetSymbolAddress((void**)&ql, g_ql);
    cudaGetSymbolAddress((void**)&kh, g_kh);
    cudaGetSymbolAddress((void**)&vh, g_vh);
    cudaGetSymbolAddress((void**)&ah, g_ah);
    cudaGetSymbolAddress((void**)&al, g_al);
    cudaGetSymbolAddress((void**)&wh, g_wh);

    cudaFuncSetAttribute(gemm_mma<1>, cudaFuncAttributeMaxDynamicSharedMemorySize, GSMEM);
    cudaFuncSetAttribute(gemm_mma<2>, cudaFuncAttributeMaxDynamicSharedMemorySize, GSMEM);
    cudaFuncSetAttribute(attn_mma, cudaFuncAttributeMaxDynamicSharedMemorySize, ATT_SMEM2);

    const int actN4 = (M_ROWS * D_) / 4;
    const int wN4   = (D_ * D_) / 4;
    dim3 gGemm(D_ / 128, M_ROWS / 128);    // (8, 64)
    const float qscale = 0.125f;           // 1/sqrt(64)

    // Q projection (pre-scaled, hi+lo output)
    split_f16<<<(actN4 + 255) / 256, 256>>>(query, ah, al, actN4);
    split_f16_hi<<<(wN4 + 255) / 256, 256>>>(w_q, wh, wN4);
    gemm_mma<1><<<gGemm, 256, GSMEM>>>(ah, al, wh, nullptr, nullptr, qh, ql, qscale);

    // K projection (hi-only output)
    split_f16<<<(actN4 + 255) / 256, 256>>>(key_, ah, al, actN4);
    split_f16_hi<<<(wN4 + 255) / 256, 256>>>(w_k, wh, wN4);
    gemm_mma<1><<<gGemm, 256, GSMEM>>>(ah, al, wh, nullptr, nullptr, kh, nullptr, 1.0f);

    // V projection (hi-only output)
    split_f16<<<(actN4 + 255) / 256, 256>>>(value, ah, al, actN4);
    split_f16_hi<<<(wN4 + 255) / 256, 256>>>(w_v, wh, wN4);
    gemm_mma<1><<<gGemm, 256, GSMEM>>>(ah, al, wh, nullptr, nullptr, vh, nullptr, 1.0f);

    // Attention (HMMA flash, fp16)
    dim3 gAtt(S_ / 128, B_ * H_);          // (16, 64)
    attn_mma<<<gAtt, 256, ATT_SMEM2>>>(qh, ql, kh, vh, gctx);

    // Output projection + bias
    split_f16<<<(actN4 + 255) / 256, 256>>>(gctx, ah, al, actN4);
    split_f16_hi<<<(wN4 + 255) / 256, 256>>>(w_o, wh, wN4);
    gemm_mma<2><<<gGemm, 256, GSMEM>>>(ah, al, wh, b_o, out, nullptr, nullptr, 1.0f);
}

// round 13
// speedup vs baseline: 4.5429x; 1.1810x over previous
#include <cuda_runtime.h>
#include <cuda_fp16.h>
#include <math.h>
#include <stdint.h>

// Problem constants
#define B_   4
#define S_   2048
#define D_   1024
#define H_   16
#define DK_  64
#define M_ROWS (B_ * S_)      // 8192

// ---------------------------------------------------------------------------
// Scratch (device globals; no allocation allowed)
// ---------------------------------------------------------------------------
__device__ __half g_a0h[(size_t)M_ROWS * D_], g_a0l[(size_t)M_ROWS * D_];
__device__ __half g_a1h[(size_t)M_ROWS * D_], g_a1l[(size_t)M_ROWS * D_];
__device__ __half g_a2h[(size_t)M_ROWS * D_], g_a2l[(size_t)M_ROWS * D_];
__device__ __half g_w0h[(size_t)D_ * D_], g_w1h[(size_t)D_ * D_];
__device__ __half g_w2h[(size_t)D_ * D_], g_w3h[(size_t)D_ * D_];
__device__ __half g_qh[(size_t)M_ROWS * D_], g_ql[(size_t)M_ROWS * D_];
__device__ __half g_kh[(size_t)M_ROWS * D_], g_vh[(size_t)M_ROWS * D_];
__device__ __half g_cxh[(size_t)M_ROWS * D_], g_cxl[(size_t)M_ROWS * D_];

// ---------------------------------------------------------------------------
// Helpers (baseline PTX only — NO tcgen05)
// ---------------------------------------------------------------------------
__device__ __forceinline__ uint32_t smem_u32(const void* p) {
    uint32_t a;
    asm("{ .reg .u64 t; cvta.to.shared.u64 t, %1; cvt.u32.u64 %0, t; }"
        : "=r"(a) : "l"(p));
    return a;
}

__device__ __forceinline__ void cp16(uint32_t dst, const void* src) {
    asm volatile("cp.async.cg.shared.global [%0], [%1], 16;" :: "r"(dst), "l"(src));
}

__device__ __forceinline__ void ldm4(uint32_t* r, uint32_t addr) {
    asm volatile("ldmatrix.sync.aligned.m8n8.x4.shared.b16 {%0,%1,%2,%3}, [%4];"
                 : "=r"(r[0]), "=r"(r[1]), "=r"(r[2]), "=r"(r[3]) : "r"(addr));
}

__device__ __forceinline__ void ldm4t(uint32_t* r, uint32_t addr) {
    asm volatile("ldmatrix.sync.aligned.m8n8.x4.trans.shared.b16 {%0,%1,%2,%3}, [%4];"
                 : "=r"(r[0]), "=r"(r[1]), "=r"(r[2]), "=r"(r[3]) : "r"(addr));
}

__device__ __forceinline__ void mma16816(float* d, const uint32_t* a, const uint32_t* b) {
    asm volatile(
        "mma.sync.aligned.m16n8k16.row.col.f32.f16.f16.f32 "
        "{%0,%1,%2,%3}, {%4,%5,%6,%7}, {%8,%9}, {%0,%1,%2,%3};"
        : "+f"(d[0]), "+f"(d[1]), "+f"(d[2]), "+f"(d[3])
        : "r"(a[0]), "r"(a[1]), "r"(a[2]), "r"(a[3]), "r"(b[0]), "r"(b[1]));
}

__device__ __forceinline__ uint32_t pack_f16x2(float a, float b) {
    __half2 h = __floats2half2_rn(a, b);
    return *(uint32_t*)&h;
}

__device__ __forceinline__ void split2_f16(float a, float b, uint32_t& hi, uint32_t& lo) {
    __half2 h = __floats2half2_rn(a, b);
    float fa = __low2float(h), fb = __high2float(h);
    __half2 l = __floats2half2_rn(a - fa, b - fb);
    hi = *(uint32_t*)&h;
    lo = *(uint32_t*)&l;
}

// ---------------------------------------------------------------------------
// Batched splits
// ---------------------------------------------------------------------------
__global__ __launch_bounds__(256)
void split_acts(const float* __restrict__ q, const float* __restrict__ k,
                const float* __restrict__ v)
{
    const int i = blockIdx.x * 256 + threadIdx.x;
    const float* in;
    __half *hi, *lo;
    if (blockIdx.y == 0)      { in = q; hi = g_a0h; lo = g_a0l; }
    else if (blockIdx.y == 1) { in = k; hi = g_a1h; lo = g_a1l; }
    else                      { in = v; hi = g_a2h; lo = g_a2l; }
    float4 val = ((const float4*)in)[i];
    uint32_t h0, l0, h1, l1;
    split2_f16(val.x, val.y, h0, l0);
    split2_f16(val.z, val.w, h1, l1);
    ((uint32_t*)hi)[2 * i] = h0;
    ((uint32_t*)hi)[2 * i + 1] = h1;
    ((uint32_t*)lo)[2 * i] = l0;
    ((uint32_t*)lo)[2 * i + 1] = l1;
}

__global__ __launch_bounds__(256)
void split_w(const float* __restrict__ wq, const float* __restrict__ wk,
             const float* __restrict__ wv, const float* __restrict__ wo)
{
    const int i = blockIdx.x * 256 + threadIdx.x;
    const float* in;
    __half* hi;
    if (blockIdx.y == 0)      { in = wq; hi = g_w0h; }
    else if (blockIdx.y == 1) { in = wk; hi = g_w1h; }
    else if (blockIdx.y == 2) { in = wv; hi = g_w2h; }
    else                      { in = wo; hi = g_w3h; }
    float4 v = ((const float4*)in)[i];
    ((uint32_t*)hi)[2 * i]     = pack_f16x2(v.x, v.y);
    ((uint32_t*)hi)[2 * i + 1] = pack_f16x2(v.z, v.w);
}

// ---------------------------------------------------------------------------
// GEMM core: 128x128 tile, BK=32, 3-stage cp.async, 1 sync per chunk.
// C = (Ah + Al) * Bh^T into fp32 acc[4][4][4].
// ---------------------------------------------------------------------------
#define GSTRIDE 40
#define MATB    (128 * GSTRIDE * 2)      // 10240
#define STAGEB  (3 * MATB)               // 30720
#define GSMEM   (3 * STAGEB)             // 92160 (3 stages -> 2 CTAs/SM)
#define NCHUNK  (D_ / 32)                // 32

__device__ __forceinline__ void gemm_core(const __half* __restrict__ Ah,
                                          const __half* __restrict__ Al,
                                          const __half* __restrict__ Bh,
                                          uint32_t sb, float acc[4][4][4])
{
    const int tid = threadIdx.x;
    const int lane = tid & 31;
    const int wid = tid >> 5;
    const int mBase = blockIdx.y * 128;
    const int nBase = blockIdx.x * 128;
    const int wm = (wid >> 2) * 64;
    const int wn = (wid & 3) * 32;

    const int lrow = tid >> 1;
    const int lch = (tid & 1) * 2;
    const __half* gAh = Ah + (size_t)(mBase + lrow) * D_ + lch * 8;
    const __half* gAl = Al + (size_t)(mBase + lrow) * D_ + lch * 8;
    const __half* gBh = Bh + (size_t)(nBase + lrow) * D_ + lch * 8;
    const uint32_t dsto = (uint32_t)(lrow * (GSTRIDE * 2) + lch * 16);

    const uint32_t a_rc = (uint32_t)((wm + (lane & 15)) * (GSTRIDE * 2) + (lane >> 4) * 16);
    const uint32_t b_rc = (uint32_t)((wn + (lane >> 4) * 8 + (lane & 7)) * (GSTRIDE * 2)
                                     + ((lane >> 3) & 1) * 16);

#define GPF(sidx, c) do { \
    const uint32_t s0_ = sb + (uint32_t)(sidx) * STAGEB; \
    const int kb_ = (c) * 32; \
    cp16(s0_ + dsto,                 gAh + kb_); \
    cp16(s0_ + dsto + 16,            gAh + kb_ + 8); \
    cp16(s0_ + MATB + dsto,          gAl + kb_); \
    cp16(s0_ + MATB + dsto + 16,     gAl + kb_ + 8); \
    cp16(s0_ + 2 * MATB + dsto,      gBh + kb_); \
    cp16(s0_ + 2 * MATB + dsto + 16, gBh + kb_ + 8); \
    asm volatile("cp.async.commit_group;" ::: "memory"); \
} while (0)

    GPF(0, 0);
    GPF(1, 1);

    int cur = 0, pf = 2;
    for (int c = 0; c < NCHUNK; ++c) {
        if (c < NCHUNK - 2)
            asm volatile("cp.async.wait_group 1;" ::: "memory");
        else
            asm volatile("cp.async.wait_group 0;" ::: "memory");
        __syncthreads();
        if (c + 2 < NCHUNK) GPF(pf, c + 2);

        const uint32_t sAh = sb + (uint32_t)cur * STAGEB;
        const uint32_t sAl = sAh + MATB;
        const uint32_t sBh = sAh + 2 * MATB;

#pragma unroll
        for (int ks = 0; ks < 2; ++ks) {
            const uint32_t kbyte = (uint32_t)(ks * 32);
            uint32_t bh[2][4];
#pragma unroll
            for (int nj = 0; nj < 2; ++nj) {
                const uint32_t boff = b_rc + kbyte + (uint32_t)(nj * 16 * GSTRIDE * 2);
                ldm4(bh[nj], sBh + boff);
            }
#pragma unroll
            for (int mi = 0; mi < 4; ++mi) {
                const uint32_t aoff = a_rc + kbyte + (uint32_t)(mi * 16 * GSTRIDE * 2);
                uint32_t ah[4], al[4];
                ldm4(ah, sAh + aoff);
                ldm4(al, sAl + aoff);
#pragma unroll
                for (int n8 = 0; n8 < 4; ++n8) {
                    const uint32_t* bhf = &bh[n8 >> 1][(n8 & 1) * 2];
                    mma16816(acc[mi][n8], ah, bhf);
                    mma16816(acc[mi][n8], al, bhf);
                }
            }
        }
        cur = (cur == 2) ? 0 : cur + 1;
        pf = (pf == 2) ? 0 : pf + 1;
    }
#undef GPF
}

// ---------------------------------------------------------------------------
// Fused QKV projection GEMM (blockIdx.z selects input/weight/output)
// ---------------------------------------------------------------------------
__global__ __launch_bounds__(256, 2)
void gemm_qkv()
{
    extern __shared__ char smc[];
    const uint32_t sb = smem_u32(smc);

    const __half *Ah, *Al, *Bh;
    __half *Chi, *Clo;
    float scale;
    if (blockIdx.z == 0)      { Ah = g_a0h; Al = g_a0l; Bh = g_w0h; Chi = g_qh; Clo = g_ql; scale = 0.125f; }
    else if (blockIdx.z == 1) { Ah = g_a1h; Al = g_a1l; Bh = g_w1h; Chi = g_kh; Clo = nullptr; scale = 1.0f; }
    else                      { Ah = g_a2h; Al = g_a2l; Bh = g_w2h; Chi = g_vh; Clo = nullptr; scale = 1.0f; }

    float acc[4][4][4];
#pragma unroll
    for (int mi = 0; mi < 4; ++mi)
#pragma unroll
        for (int nj = 0; nj < 4; ++nj)
#pragma unroll
            for (int e = 0; e < 4; ++e) acc[mi][nj][e] = 0.0f;

    gemm_core(Ah, Al, Bh, sb, acc);

    const int lane = threadIdx.x & 31;
    const int wid = threadIdx.x >> 5;
    const int mBase = blockIdx.y * 128;
    const int nBase = blockIdx.x * 128;
    const int wm = (wid >> 2) * 64;
    const int wn = (wid & 3) * 32;
    const int g = lane >> 2;
    const int i2 = (lane & 3) * 2;

#pragma unroll
    for (int mi = 0; mi < 4; ++mi) {
#pragma unroll
        for (int n8 = 0; n8 < 4; ++n8) {
            const int row0 = mBase + wm + mi * 16 + g;
            const int row1 = row0 + 8;
            const int col = nBase + wn + n8 * 8 + i2;
            float v00 = acc[mi][n8][0] * scale, v01 = acc[mi][n8][1] * scale;
            float v10 = acc[mi][n8][2] * scale, v11 = acc[mi][n8][3] * scale;
            const int h = col >> 6;
            const int d0 = col & 63;
            const int b0i = row0 >> 11, s0i = row0 & 2047;
            const int b1i = row1 >> 11, s1i = row1 & 2047;
            const size_t o0 = ((((size_t)(b0i * H_ + h)) * S_ + s0i) * DK_ + d0) >> 1;
            const size_t o1 = ((((size_t)(b1i * H_ + h)) * S_ + s1i) * DK_ + d0) >> 1;
            if (Clo) {
                uint32_t h0, l0, h1, l1;
                split2_f16(v00, v01, h0, l0);
                split2_f16(v10, v11, h1, l1);
                ((uint32_t*)Chi)[o0] = h0;
                ((uint32_t*)Chi)[o1] = h1;
                ((uint32_t*)Clo)[o0] = l0;
                ((uint32_t*)Clo)[o1] = l1;
            } else {
                ((uint32_t*)Chi)[o0] = pack_f16x2(v00, v01);
                ((uint32_t*)Chi)[o1] = pack_f16x2(v10, v11);
            }
        }
    }
}

// ---------------------------------------------------------------------------
// Output projection GEMM + bias -> fp32 out
// ---------------------------------------------------------------------------
__global__ __launch_bounds__(256, 2)
void gemm_out(const float* __restrict__ bias, float* __restrict__ out)
{
    extern __shared__ char smc[];
    const uint32_t sb = smem_u32(smc);

    float acc[4][4][4];
#pragma unroll
    for (int mi = 0; mi < 4; ++mi)
#pragma unroll
        for (int nj = 0; nj < 4; ++nj)
#pragma unroll
            for (int e = 0; e < 4; ++e) acc[mi][nj][e] = 0.0f;

    gemm_core(g_cxh, g_cxl, g_w3h, sb, acc);

    const int lane = threadIdx.x & 31;
    const int wid = threadIdx.x >> 5;
    const int mBase = blockIdx.y * 128;
    const int nBase = blockIdx.x * 128;
    const int wm = (wid >> 2) * 64;
    const int wn = (wid & 3) * 32;
    const int g = lane >> 2;
    const int i2 = (lane & 3) * 2;

#pragma unroll
    for (int mi = 0; mi < 4; ++mi) {
#pragma unroll
        for (int n8 = 0; n8 < 4; ++n8) {
            const int row0 = mBase + wm + mi * 16 + g;
            const int row1 = row0 + 8;
            const int col = nBase + wn + n8 * 8 + i2;
            const float bx = bias[col], by = bias[col + 1];
            float2 o0, o1;
            o0.x = acc[mi][n8][0] + bx; o0.y = acc[mi][n8][1] + by;
            o1.x = acc[mi][n8][2] + bx; o1.y = acc[mi][n8][3] + by;
            *(float2*)(out + (size_t)row0 * D_ + col) = o0;
            *(float2*)(out + (size_t)row1 * D_ + col) = o1;
        }
    }
}

// ---------------------------------------------------------------------------
// HMMA flash attention: swizzled 128B rows, 64-key tiles, 2 CTAs/SM,
// 1 sync/iter, epilogue writes ctx as fp16 hi/lo directly.
// ---------------------------------------------------------------------------
#define ATT_SMEM 65536
#define SWZ(row, ch) ((uint32_t)((row) * 128 + ((((ch)) ^ ((row) & 7)) << 4)))

__global__ __launch_bounds__(256, 2)
void attn_mma()
{
    extern __shared__ char smc[];
    const uint32_t sb = smem_u32(smc);
    const int tid = threadIdx.x;
    const int lane = tid & 31;
    const int wid = tid >> 5;
    const int bh = blockIdx.y;          // 0..63
    const int qt = blockIdx.x;          // 0..15

    const size_t qoff = ((size_t)bh * S_ + qt * 128) * DK_;
    const size_t kvoff = (size_t)bh * S_ * DK_;

    // prologue: Q (hi/lo) + K/V stage 0 — one commit group
    {
#pragma unroll
        for (int j = 0; j < 4; ++j) {
            const int task = tid + 256 * j;
            const int row = task >> 3, ch = task & 7;
            const uint32_t so = SWZ(row, ch);
            cp16(sb + so,         g_qh + qoff + (size_t)row * DK_ + ch * 8);
            cp16(sb + 16384 + so, g_ql + qoff + (size_t)row * DK_ + ch * 8);
        }
#pragma unroll
        for (int j = 0; j < 2; ++j) {
            const int task = tid + 256 * j;
            const int row = task >> 3, ch = task & 7;
            const uint32_t so = SWZ(row, ch);
            cp16(sb + 32768 + so,        g_kh + kvoff + (size_t)row * DK_ + ch * 8);
            cp16(sb + 32768 + 8192 + so, g_vh + kvoff + (size_t)row * DK_ + ch * 8);
        }
        asm volatile("cp.async.commit_group;" ::: "memory");
    }

    uint32_t qfh[4][4], qfl[4][4];
    float o[8][4];
#pragma unroll
    for (int f = 0; f < 8; ++f)
#pragma unroll
        for (int e = 0; e < 4; ++e) o[f][e] = 0.0f;
    float mrow[2] = {-INFINITY, -INFINITY};
    float lrow[2] = {0.0f, 0.0f};

    // lane-derived constants
    const int qrow = wid * 16 + (lane & 15);
    const int qch0 = lane >> 4;
    const int krow0 = ((lane >> 4) << 3) + (lane & 7);
    const int kch0 = (lane >> 3) & 1;
    const int vrow0 = lane & 15;
    const int vch0 = lane >> 4;

    for (int kt = 0; kt < 32; ++kt) {
        asm volatile("cp.async.wait_group 0;" ::: "memory");
        __syncthreads();

        if (kt == 0) {
#pragma unroll
            for (int kc = 0; kc < 4; ++kc) {
                ldm4(qfh[kc], sb + SWZ(qrow, qch0 + kc * 2));
                ldm4(qfl[kc], sb + 16384 + SWZ(qrow, qch0 + kc * 2));
            }
        }

        if (kt + 1 < 32) {
            const uint32_t st = sb + 32768 + (uint32_t)(((kt + 1) & 1) * 16384);
            const size_t base = kvoff + (size_t)(kt + 1) * 64 * DK_;
#pragma unroll
            for (int j = 0; j < 2; ++j) {
                const int task = tid + 256 * j;
                const int row = task >> 3, ch = task & 7;
                const uint32_t so = SWZ(row, ch);
                cp16(st + so,        g_kh + base + (size_t)row * DK_ + ch * 8);
                cp16(st + 8192 + so, g_vh + base + (size_t)row * DK_ + ch * 8);
            }
            asm volatile("cp.async.commit_group;" ::: "memory");
        }

        const uint32_t sK = sb + 32768 + (uint32_t)((kt & 1) * 16384);
        const uint32_t sV = sK + 8192;

        // ---- S = Q K^T over 64 keys ----
        float sc[8][4];
#pragma unroll
        for (int f = 0; f < 8; ++f)
#pragma unroll
            for (int e = 0; e < 4; ++e) sc[f][e] = 0.0f;

#pragma unroll
        for (int kc = 0; kc < 4; ++kc) {
#pragma unroll
            for (int n16 = 0; n16 < 4; ++n16) {
                uint32_t kh4[4];
                ldm4(kh4, sK + SWZ(krow0 + n16 * 16, kch0 + kc * 2));
                mma16816(sc[2 * n16],     qfh[kc], kh4);
                mma16816(sc[2 * n16],     qfl[kc], kh4);
                mma16816(sc[2 * n16 + 1], qfh[kc], kh4 + 2);
                mma16816(sc[2 * n16 + 1], qfl[kc], kh4 + 2);
            }
        }

        // ---- online softmax (rows g and g+8) ----
#pragma unroll
        for (int r = 0; r < 2; ++r) {
            const int e0 = r * 2, e1 = r * 2 + 1;
            float rmax = -INFINITY;
#pragma unroll
            for (int f = 0; f < 8; ++f)
                rmax = fmaxf(rmax, fmaxf(sc[f][e0], sc[f][e1]));
            rmax = fmaxf(rmax, __shfl_xor_sync(0xffffffffu, rmax, 1));
            rmax = fmaxf(rmax, __shfl_xor_sync(0xffffffffu, rmax, 2));
            const float mnew = fmaxf(mrow[r], rmax);
            const float corr = __expf(mrow[r] - mnew);
            float rsum = 0.0f;
#pragma unroll
            for (int f = 0; f < 8; ++f) {
                float p0 = __expf(sc[f][e0] - mnew);
                float p1 = __expf(sc[f][e1] - mnew);
                sc[f][e0] = p0; sc[f][e1] = p1;
                rsum += p0 + p1;
            }
            rsum += __shfl_xor_sync(0xffffffffu, rsum, 1);
            rsum += __shfl_xor_sync(0xffffffffu, rsum, 2);
            lrow[r] = lrow[r] * corr + rsum;
            mrow[r] = mnew;
#pragma unroll
            for (int f = 0; f < 8; ++f) {
                o[f][e0] *= corr;
                o[f][e1] *= corr;
            }
        }

        // ---- pack P into fp16 hi/lo a-frags (in place over sc) ----
        uint32_t* pp = (uint32_t*)&sc[0][0];
#pragma unroll
        for (int kk = 0; kk < 4; ++kk) {
            const float p00 = sc[2 * kk][0],     p01 = sc[2 * kk][1];
            const float p02 = sc[2 * kk][2],     p03 = sc[2 * kk][3];
            const float p10 = sc[2 * kk + 1][0], p11 = sc[2 * kk + 1][1];
            const float p12 = sc[2 * kk + 1][2], p13 = sc[2 * kk + 1][3];
            uint32_t h0, l0, h1, l1, h2, l2, h3, l3;
            split2_f16(p00, p01, h0, l0);
            split2_f16(p02, p03, h1, l1);
            split2_f16(p10, p11, h2, l2);
            split2_f16(p12, p13, h3, l3);
            pp[kk * 8 + 0] = h0; pp[kk * 8 + 1] = h1;
            pp[kk * 8 + 2] = h2; pp[kk * 8 + 3] = h3;
            pp[kk * 8 + 4] = l0; pp[kk * 8 + 5] = l1;
            pp[kk * 8 + 6] = l2; pp[kk * 8 + 7] = l3;
        }

        // ---- O += P V ----
#pragma unroll
        for (int kk = 0; kk < 4; ++kk) {
            const uint32_t* aPh = &pp[kk * 8];
            const uint32_t* aPl = &pp[kk * 8 + 4];
#pragma unroll
            for (int n16 = 0; n16 < 4; ++n16) {
                uint32_t vh4[4];
                ldm4t(vh4, sV + SWZ(vrow0 + kk * 16, vch0 + n16 * 2));
                mma16816(o[2 * n16],     aPh, vh4);
                mma16816(o[2 * n16],     aPl, vh4);
                mma16816(o[2 * n16 + 1], aPh, vh4 + 2);
                mma16816(o[2 * n16 + 1], aPl, vh4 + 2);
            }
        }
    }

    // ---- epilogue: normalize and write ctx hi/lo [B,S,D] ----
    const int bb = bh >> 4;
    const int hh = bh & 15;
    const int g = lane >> 2;
    const int i2 = (lane & 3) * 2;
    const int s0 = qt * 128 + wid * 16 + g;
    const int s1 = s0 + 8;
    const float inv0 = 1.0f / lrow[0];
    const float inv1 = 1.0f / lrow[1];
#pragma unroll
    for (int f = 0; f < 8; ++f) {
        const int d = f * 8 + i2;
        const size_t i0 = ((((size_t)(bb * S_ + s0)) * H_ + hh) * DK_ + d) >> 1;
        const size_t i1 = ((((size_t)(bb * S_ + s1)) * H_ + hh) * DK_ + d) >> 1;
        uint32_t h, l;
        split2_f16(o[f][0] * inv0, o[f][1] * inv0, h, l);
        ((uint32_t*)g_cxh)[i0] = h;
        ((uint32_t*)g_cxl)[i0] = l;
        split2_f16(o[f][2] * inv1, o[f][3] * inv1, h, l);
        ((uint32_t*)g_cxh)[i1] = h;
        ((uint32_t*)g_cxl)[i1] = l;
    }
}

// ---------------------------------------------------------------------------
// Launcher (5 launches)
// ---------------------------------------------------------------------------
extern "C" void kernel_launch(void* const* d_in, const int* in_sizes, int n_in,
                              void* d_out, int out_size)
{
    const float* query = (const float*)d_in[0];
    const float* key_  = (const float*)d_in[1];
    const float* value = (const float*)d_in[2];
    const float* w_q   = (const float*)d_in[3];
    const float* w_k   = (const float*)d_in[4];
    const float* w_v   = (const float*)d_in[5];
    const float* w_o   = (const float*)d_in[6];
    const float* b_o   = (const float*)d_in[7];
    float* out = (float*)d_out;

    cudaFuncSetAttribute(gemm_qkv, cudaFuncAttributeMaxDynamicSharedMemorySize, GSMEM);
    cudaFuncSetAttribute(gemm_out, cudaFuncAttributeMaxDynamicSharedMemorySize, GSMEM);
    cudaFuncSetAttribute(attn_mma, cudaFuncAttributeMaxDynamicSharedMemorySize, ATT_SMEM);

    const int actN4 = (M_ROWS * D_) / 4;   // 2097152 -> 8192 blocks
    const int wN4   = (D_ * D_) / 4;       // 262144  -> 1024 blocks

    split_acts<<<dim3(actN4 / 256, 3), 256>>>(query, key_, value);
    split_w<<<dim3(wN4 / 256, 4), 256>>>(w_q, w_k, w_v, w_o);

    gemm_qkv<<<dim3(D_ / 128, M_ROWS / 128, 3), 256, GSMEM>>>();

    attn_mma<<<dim3(S_ / 128, B_ * H_), 256, ATT_SMEM>>>();

    gemm_out<<<dim3(D_ / 128, M_ROWS / 128), 256, GSMEM>>>(b_o, out);
}

// round 14
// speedup vs baseline: 5.7360x; 1.2626x over previous
#include <cuda_runtime.h>
#include <cuda_fp16.h>
#include <math.h>
#include <stdint.h>

// Problem constants
#define B_   4
#define S_   2048
#define D_   1024
#define H_   16
#define DK_  64
#define M_ROWS (B_ * S_)      // 8192

// ---------------------------------------------------------------------------
// Scratch (device globals; no allocation allowed)
// ---------------------------------------------------------------------------
__device__ __half g_a0h[(size_t)M_ROWS * D_];
__device__ __half g_a1h[(size_t)M_ROWS * D_];
__device__ __half g_a2h[(size_t)M_ROWS * D_];
__device__ __half g_w0h[(size_t)D_ * D_], g_w1h[(size_t)D_ * D_];
__device__ __half g_w2h[(size_t)D_ * D_], g_w3h[(size_t)D_ * D_];
__device__ __half g_qh[(size_t)M_ROWS * D_], g_ql[(size_t)M_ROWS * D_];
__device__ __half g_kh[(size_t)M_ROWS * D_], g_vh[(size_t)M_ROWS * D_];
__device__ __half g_cxh[(size_t)M_ROWS * D_];

// ---------------------------------------------------------------------------
// Helpers (baseline PTX only — NO tcgen05)
// ---------------------------------------------------------------------------
__device__ __forceinline__ uint32_t smem_u32(const void* p) {
    uint32_t a;
    asm("{ .reg .u64 t; cvta.to.shared.u64 t, %1; cvt.u32.u64 %0, t; }"
        : "=r"(a) : "l"(p));
    return a;
}

__device__ __forceinline__ void cp16(uint32_t dst, const void* src) {
    asm volatile("cp.async.cg.shared.global [%0], [%1], 16;" :: "r"(dst), "l"(src));
}

__device__ __forceinline__ void ldm4(uint32_t* r, uint32_t addr) {
    asm volatile("ldmatrix.sync.aligned.m8n8.x4.shared.b16 {%0,%1,%2,%3}, [%4];"
                 : "=r"(r[0]), "=r"(r[1]), "=r"(r[2]), "=r"(r[3]) : "r"(addr));
}

__device__ __forceinline__ void ldm4t(uint32_t* r, uint32_t addr) {
    asm volatile("ldmatrix.sync.aligned.m8n8.x4.trans.shared.b16 {%0,%1,%2,%3}, [%4];"
                 : "=r"(r[0]), "=r"(r[1]), "=r"(r[2]), "=r"(r[3]) : "r"(addr));
}

__device__ __forceinline__ void mma16816(float* d, const uint32_t* a, const uint32_t* b) {
    asm volatile(
        "mma.sync.aligned.m16n8k16.row.col.f32.f16.f16.f32 "
        "{%0,%1,%2,%3}, {%4,%5,%6,%7}, {%8,%9}, {%0,%1,%2,%3};"
        : "+f"(d[0]), "+f"(d[1]), "+f"(d[2]), "+f"(d[3])
        : "r"(a[0]), "r"(a[1]), "r"(a[2]), "r"(a[3]), "r"(b[0]), "r"(b[1]));
}

__device__ __forceinline__ uint32_t pack_f16x2(float a, float b) {
    __half2 h = __floats2half2_rn(a, b);
    return *(uint32_t*)&h;
}

__device__ __forceinline__ void split2_f16(float a, float b, uint32_t& hi, uint32_t& lo) {
    __half2 h = __floats2half2_rn(a, b);
    float fa = __low2float(h), fb = __high2float(h);
    __half2 l = __floats2half2_rn(a - fa, b - fb);
    hi = *(uint32_t*)&h;
    lo = *(uint32_t*)&l;
}

// ---------------------------------------------------------------------------
// Batched hi-only splits (acts + weights)
// ---------------------------------------------------------------------------
__global__ __launch_bounds__(256)
void split_acts(const float* __restrict__ q, const float* __restrict__ k,
                const float* __restrict__ v)
{
    const int i = blockIdx.x * 256 + threadIdx.x;
    const float* in;
    __half* hi;
    if (blockIdx.y == 0)      { in = q; hi = g_a0h; }
    else if (blockIdx.y == 1) { in = k; hi = g_a1h; }
    else                      { in = v; hi = g_a2h; }
    float4 val = ((const float4*)in)[i];
    ((uint32_t*)hi)[2 * i]     = pack_f16x2(val.x, val.y);
    ((uint32_t*)hi)[2 * i + 1] = pack_f16x2(val.z, val.w);
}

__global__ __launch_bounds__(256)
void split_w(const float* __restrict__ wq, const float* __restrict__ wk,
             const float* __restrict__ wv, const float* __restrict__ wo)
{
    const int i = blockIdx.x * 256 + threadIdx.x;
    const float* in;
    __half* hi;
    if (blockIdx.y == 0)      { in = wq; hi = g_w0h; }
    else if (blockIdx.y == 1) { in = wk; hi = g_w1h; }
    else if (blockIdx.y == 2) { in = wv; hi = g_w2h; }
    else                      { in = wo; hi = g_w3h; }
    float4 v = ((const float4*)in)[i];
    ((uint32_t*)hi)[2 * i]     = pack_f16x2(v.x, v.y);
    ((uint32_t*)hi)[2 * i + 1] = pack_f16x2(v.z, v.w);
}

// ---------------------------------------------------------------------------
// GEMM core: 128x128 tile, BK=32, 3-stage cp.async, 1 sync per chunk.
// C = Ah * Bh^T into fp32 acc[4][4][4]. (single-pass fp16)
// ---------------------------------------------------------------------------
#define GSTRIDE 40
#define MATB    (128 * GSTRIDE * 2)      // 10240
#define STAGEB  (2 * MATB)               // 20480 (Ah, Bh)
#define GSMEM   (3 * STAGEB)             // 61440
#define NCHUNK  (D_ / 32)                // 32

__device__ __forceinline__ void gemm_core(const __half* __restrict__ Ah,
                                          const __half* __restrict__ Bh,
                                          uint32_t sb, float acc[4][4][4])
{
    const int tid = threadIdx.x;
    const int lane = tid & 31;
    const int wid = tid >> 5;
    const int mBase = blockIdx.y * 128;
    const int nBase = blockIdx.x * 128;
    const int wm = (wid >> 2) * 64;
    const int wn = (wid & 3) * 32;

    const int lrow = tid >> 1;
    const int lch = (tid & 1) * 2;
    const __half* gAh = Ah + (size_t)(mBase + lrow) * D_ + lch * 8;
    const __half* gBh = Bh + (size_t)(nBase + lrow) * D_ + lch * 8;
    const uint32_t dsto = (uint32_t)(lrow * (GSTRIDE * 2) + lch * 16);

    const uint32_t a_rc = (uint32_t)((wm + (lane & 15)) * (GSTRIDE * 2) + (lane >> 4) * 16);
    const uint32_t b_rc = (uint32_t)((wn + (lane >> 4) * 8 + (lane & 7)) * (GSTRIDE * 2)
                                     + ((lane >> 3) & 1) * 16);

#define GPF(sidx, c) do { \
    const uint32_t s0_ = sb + (uint32_t)(sidx) * STAGEB; \
    const int kb_ = (c) * 32; \
    cp16(s0_ + dsto,             gAh + kb_); \
    cp16(s0_ + dsto + 16,        gAh + kb_ + 8); \
    cp16(s0_ + MATB + dsto,      gBh + kb_); \
    cp16(s0_ + MATB + dsto + 16, gBh + kb_ + 8); \
    asm volatile("cp.async.commit_group;" ::: "memory"); \
} while (0)

    GPF(0, 0);
    GPF(1, 1);

    int cur = 0, pf = 2;
    for (int c = 0; c < NCHUNK; ++c) {
        if (c < NCHUNK - 2)
            asm volatile("cp.async.wait_group 1;" ::: "memory");
        else
            asm volatile("cp.async.wait_group 0;" ::: "memory");
        __syncthreads();
        if (c + 2 < NCHUNK) GPF(pf, c + 2);

        const uint32_t sAh = sb + (uint32_t)cur * STAGEB;
        const uint32_t sBh = sAh + MATB;

#pragma unroll
        for (int ks = 0; ks < 2; ++ks) {
            const uint32_t kbyte = (uint32_t)(ks * 32);
            uint32_t bh[2][4];
#pragma unroll
            for (int nj = 0; nj < 2; ++nj) {
                const uint32_t boff = b_rc + kbyte + (uint32_t)(nj * 16 * GSTRIDE * 2);
                ldm4(bh[nj], sBh + boff);
            }
#pragma unroll
            for (int mi = 0; mi < 4; ++mi) {
                const uint32_t aoff = a_rc + kbyte + (uint32_t)(mi * 16 * GSTRIDE * 2);
                uint32_t ah[4];
                ldm4(ah, sAh + aoff);
#pragma unroll
                for (int n8 = 0; n8 < 4; ++n8) {
                    const uint32_t* bhf = &bh[n8 >> 1][(n8 & 1) * 2];
                    mma16816(acc[mi][n8], ah, bhf);
                }
            }
        }
        cur = (cur == 2) ? 0 : cur + 1;
        pf = (pf == 2) ? 0 : pf + 1;
    }
#undef GPF
}

// ---------------------------------------------------------------------------
// Fused QKV projection GEMM (blockIdx.z selects input/weight/output)
// ---------------------------------------------------------------------------
__global__ __launch_bounds__(256, 2)
void gemm_qkv()
{
    extern __shared__ char smc[];
    const uint32_t sb = smem_u32(smc);

    const __half *Ah, *Bh;
    __half *Chi, *Clo;
    float scale;
    if (blockIdx.z == 0)      { Ah = g_a0h; Bh = g_w0h; Chi = g_qh; Clo = g_ql; scale = 0.125f; }
    else if (blockIdx.z == 1) { Ah = g_a1h; Bh = g_w1h; Chi = g_kh; Clo = nullptr; scale = 1.0f; }
    else                      { Ah = g_a2h; Bh = g_w2h; Chi = g_vh; Clo = nullptr; scale = 1.0f; }

    float acc[4][4][4];
#pragma unroll
    for (int mi = 0; mi < 4; ++mi)
#pragma unroll
        for (int nj = 0; nj < 4; ++nj)
#pragma unroll
            for (int e = 0; e < 4; ++e) acc[mi][nj][e] = 0.0f;

    gemm_core(Ah, Bh, sb, acc);

    const int lane = threadIdx.x & 31;
    const int wid = threadIdx.x >> 5;
    const int mBase = blockIdx.y * 128;
    const int nBase = blockIdx.x * 128;
    const int wm = (wid >> 2) * 64;
    const int wn = (wid & 3) * 32;
    const int g = lane >> 2;
    const int i2 = (lane & 3) * 2;

#pragma unroll
    for (int mi = 0; mi < 4; ++mi) {
#pragma unroll
        for (int n8 = 0; n8 < 4; ++n8) {
            const int row0 = mBase + wm + mi * 16 + g;
            const int row1 = row0 + 8;
            const int col = nBase + wn + n8 * 8 + i2;
            float v00 = acc[mi][n8][0] * scale, v01 = acc[mi][n8][1] * scale;
            float v10 = acc[mi][n8][2] * scale, v11 = acc[mi][n8][3] * scale;
            const int h = col >> 6;
            const int d0 = col & 63;
            const int b0i = row0 >> 11, s0i = row0 & 2047;
            const int b1i = row1 >> 11, s1i = row1 & 2047;
            const size_t o0 = ((((size_t)(b0i * H_ + h)) * S_ + s0i) * DK_ + d0) >> 1;
            const size_t o1 = ((((size_t)(b1i * H_ + h)) * S_ + s1i) * DK_ + d0) >> 1;
            if (Clo) {
                uint32_t h0, l0, h1, l1;
                split2_f16(v00, v01, h0, l0);
                split2_f16(v10, v11, h1, l1);
                ((uint32_t*)Chi)[o0] = h0;
                ((uint32_t*)Chi)[o1] = h1;
                ((uint32_t*)Clo)[o0] = l0;
                ((uint32_t*)Clo)[o1] = l1;
            } else {
                ((uint32_t*)Chi)[o0] = pack_f16x2(v00, v01);
                ((uint32_t*)Chi)[o1] = pack_f16x2(v10, v11);
            }
        }
    }
}

// ---------------------------------------------------------------------------
// Output projection GEMM + bias -> fp32 out
// ---------------------------------------------------------------------------
__global__ __launch_bounds__(256, 2)
void gemm_out(const float* __restrict__ bias, float* __restrict__ out)
{
    extern __shared__ char smc[];
    const uint32_t sb = smem_u32(smc);

    float acc[4][4][4];
#pragma unroll
    for (int mi = 0; mi < 4; ++mi)
#pragma unroll
        for (int nj = 0; nj < 4; ++nj)
#pragma unroll
            for (int e = 0; e < 4; ++e) acc[mi][nj][e] = 0.0f;

    gemm_core(g_cxh, g_w3h, sb, acc);

    const int lane = threadIdx.x & 31;
    const int wid = threadIdx.x >> 5;
    const int mBase = blockIdx.y * 128;
    const int nBase = blockIdx.x * 128;
    const int wm = (wid >> 2) * 64;
    const int wn = (wid & 3) * 32;
    const int g = lane >> 2;
    const int i2 = (lane & 3) * 2;

#pragma unroll
    for (int mi = 0; mi < 4; ++mi) {
#pragma unroll
        for (int n8 = 0; n8 < 4; ++n8) {
            const int row0 = mBase + wm + mi * 16 + g;
            const int row1 = row0 + 8;
            const int col = nBase + wn + n8 * 8 + i2;
            const float bx = bias[col], by = bias[col + 1];
            float2 o0, o1;
            o0.x = acc[mi][n8][0] + bx; o0.y = acc[mi][n8][1] + by;
            o1.x = acc[mi][n8][2] + bx; o1.y = acc[mi][n8][3] + by;
            *(float2*)(out + (size_t)row0 * D_ + col) = o0;
            *(float2*)(out + (size_t)row1 * D_ + col) = o1;
        }
    }
}

// ---------------------------------------------------------------------------
// HMMA flash attention: swizzled 128B rows, 64-key tiles, 2 CTAs/SM,
// 1 sync/iter. Q 2-pass, P 2-pass (precision hedge). ctx written hi-only.
// ---------------------------------------------------------------------------
#define ATT_SMEM 65536
#define SWZ(row, ch) ((uint32_t)((row) * 128 + ((((ch)) ^ ((row) & 7)) << 4)))

__global__ __launch_bounds__(256, 2)
void attn_mma()
{
    extern __shared__ char smc[];
    const uint32_t sb = smem_u32(smc);
    const int tid = threadIdx.x;
    const int lane = tid & 31;
    const int wid = tid >> 5;
    const int bh = blockIdx.y;          // 0..63
    const int qt = blockIdx.x;          // 0..15

    const size_t qoff = ((size_t)bh * S_ + qt * 128) * DK_;
    const size_t kvoff = (size_t)bh * S_ * DK_;

    // prologue: Q (hi/lo) + K/V stage 0 — one commit group
    {
#pragma unroll
        for (int j = 0; j < 4; ++j) {
            const int task = tid + 256 * j;
            const int row = task >> 3, ch = task & 7;
            const uint32_t so = SWZ(row, ch);
            cp16(sb + so,         g_qh + qoff + (size_t)row * DK_ + ch * 8);
            cp16(sb + 16384 + so, g_ql + qoff + (size_t)row * DK_ + ch * 8);
        }
#pragma unroll
        for (int j = 0; j < 2; ++j) {
            const int task = tid + 256 * j;
            const int row = task >> 3, ch = task & 7;
            const uint32_t so = SWZ(row, ch);
            cp16(sb + 32768 + so,        g_kh + kvoff + (size_t)row * DK_ + ch * 8);
            cp16(sb + 32768 + 8192 + so, g_vh + kvoff + (size_t)row * DK_ + ch * 8);
        }
        asm volatile("cp.async.commit_group;" ::: "memory");
    }

    uint32_t qfh[4][4], qfl[4][4];
    float o[8][4];
#pragma unroll
    for (int f = 0; f < 8; ++f)
#pragma unroll
        for (int e = 0; e < 4; ++e) o[f][e] = 0.0f;
    float mrow[2] = {-INFINITY, -INFINITY};
    float lrow[2] = {0.0f, 0.0f};

    const int qrow = wid * 16 + (lane & 15);
    const int qch0 = lane >> 4;
    const int krow0 = ((lane >> 4) << 3) + (lane & 7);
    const int kch0 = (lane >> 3) & 1;
    const int vrow0 = lane & 15;
    const int vch0 = lane >> 4;

    for (int kt = 0; kt < 32; ++kt) {
        asm volatile("cp.async.wait_group 0;" ::: "memory");
        __syncthreads();

        if (kt == 0) {
#pragma unroll
            for (int kc = 0; kc < 4; ++kc) {
                ldm4(qfh[kc], sb + SWZ(qrow, qch0 + kc * 2));
                ldm4(qfl[kc], sb + 16384 + SWZ(qrow, qch0 + kc * 2));
            }
        }

        if (kt + 1 < 32) {
            const uint32_t st = sb + 32768 + (uint32_t)(((kt + 1) & 1) * 16384);
            const size_t base = kvoff + (size_t)(kt + 1) * 64 * DK_;
#pragma unroll
            for (int j = 0; j < 2; ++j) {
                const int task = tid + 256 * j;
                const int row = task >> 3, ch = task & 7;
                const uint32_t so = SWZ(row, ch);
                cp16(st + so,        g_kh + base + (size_t)row * DK_ + ch * 8);
                cp16(st + 8192 + so, g_vh + base + (size_t)row * DK_ + ch * 8);
            }
            asm volatile("cp.async.commit_group;" ::: "memory");
        }

        const uint32_t sK = sb + 32768 + (uint32_t)((kt & 1) * 16384);
        const uint32_t sV = sK + 8192;

        // ---- S = Q K^T over 64 keys ----
        float sc[8][4];
#pragma unroll
        for (int f = 0; f < 8; ++f)
#pragma unroll
            for (int e = 0; e < 4; ++e) sc[f][e] = 0.0f;

#pragma unroll
        for (int kc = 0; kc < 4; ++kc) {
#pragma unroll
            for (int n16 = 0; n16 < 4; ++n16) {
                uint32_t kh4[4];
                ldm4(kh4, sK + SWZ(krow0 + n16 * 16, kch0 + kc * 2));
                mma16816(sc[2 * n16],     qfh[kc], kh4);
                mma16816(sc[2 * n16],     qfl[kc], kh4);
                mma16816(sc[2 * n16 + 1], qfh[kc], kh4 + 2);
                mma16816(sc[2 * n16 + 1], qfl[kc], kh4 + 2);
            }
        }

        // ---- online softmax (rows g and g+8) ----
#pragma unroll
        for (int r = 0; r < 2; ++r) {
            const int e0 = r * 2, e1 = r * 2 + 1;
            float rmax = -INFINITY;
#pragma unroll
            for (int f = 0; f < 8; ++f)
                rmax = fmaxf(rmax, fmaxf(sc[f][e0], sc[f][e1]));
            rmax = fmaxf(rmax, __shfl_xor_sync(0xffffffffu, rmax, 1));
            rmax = fmaxf(rmax, __shfl_xor_sync(0xffffffffu, rmax, 2));
            const float mnew = fmaxf(mrow[r], rmax);
            const float corr = __expf(mrow[r] - mnew);
            float rsum = 0.0f;
#pragma unroll
            for (int f = 0; f < 8; ++f) {
                float p0 = __expf(sc[f][e0] - mnew);
                float p1 = __expf(sc[f][e1] - mnew);
                sc[f][e0] = p0; sc[f][e1] = p1;
                rsum += p0 + p1;
            }
            rsum += __shfl_xor_sync(0xffffffffu, rsum, 1);
            rsum += __shfl_xor_sync(0xffffffffu, rsum, 2);
            lrow[r] = lrow[r] * corr + rsum;
            mrow[r] = mnew;
#pragma unroll
            for (int f = 0; f < 8; ++f) {
                o[f][e0] *= corr;
                o[f][e1] *= corr;
            }
        }

        // ---- pack P into fp16 hi/lo a-frags (in place over sc) ----
        uint32_t* pp = (uint32_t*)&sc[0][0];
#pragma unroll
        for (int kk = 0; kk < 4; ++kk) {
            const float p00 = sc[2 * kk][0],     p01 = sc[2 * kk][1];
            const float p02 = sc[2 * kk][2],     p03 = sc[2 * kk][3];
            const float p10 = sc[2 * kk + 1][0], p11 = sc[2 * kk + 1][1];
            const float p12 = sc[2 * kk + 1][2], p13 = sc[2 * kk + 1][3];
            uint32_t h0, l0, h1, l1, h2, l2, h3, l3;
            split2_f16(p00, p01, h0, l0);
            split2_f16(p02, p03, h1, l1);
            split2_f16(p10, p11, h2, l2);
            split2_f16(p12, p13, h3, l3);
            pp[kk * 8 + 0] = h0; pp[kk * 8 + 1] = h1;
            pp[kk * 8 + 2] = h2; pp[kk * 8 + 3] = h3;
            pp[kk * 8 + 4] = l0; pp[kk * 8 + 5] = l1;
            pp[kk * 8 + 6] = l2; pp[kk * 8 + 7] = l3;
        }

        // ---- O += P V ----
#pragma unroll
        for (int kk = 0; kk < 4; ++kk) {
            const uint32_t* aPh = &pp[kk * 8];
            const uint32_t* aPl = &pp[kk * 8 + 4];
#pragma unroll
            for (int n16 = 0; n16 < 4; ++n16) {
                uint32_t vh4[4];
                ldm4t(vh4, sV + SWZ(vrow0 + kk * 16, vch0 + n16 * 2));
                mma16816(o[2 * n16],     aPh, vh4);
                mma16816(o[2 * n16],     aPl, vh4);
                mma16816(o[2 * n16 + 1], aPh, vh4 + 2);
                mma16816(o[2 * n16 + 1], aPl, vh4 + 2);
            }
        }
    }

    // ---- epilogue: normalize and write ctx hi [B,S,D] ----
    const int bb = bh >> 4;
    const int hh = bh & 15;
    const int g = lane >> 2;
    const int i2 = (lane & 3) * 2;
    const int s0 = qt * 128 + wid * 16 + g;
    const int s1 = s0 + 8;
    const float inv0 = 1.0f / lrow[0];
    const float inv1 = 1.0f / lrow[1];
#pragma unroll
    for (int f = 0; f < 8; ++f) {
        const int d = f * 8 + i2;
        const size_t i0 = ((((size_t)(bb * S_ + s0)) * H_ + hh) * DK_ + d) >> 1;
        const size_t i1 = ((((size_t)(bb * S_ + s1)) * H_ + hh) * DK_ + d) >> 1;
        ((uint32_t*)g_cxh)[i0] = pack_f16x2(o[f][0] * inv0, o[f][1] * inv0);
        ((uint32_t*)g_cxh)[i1] = pack_f16x2(o[f][2] * inv1, o[f][3] * inv1);
    }
}

// ---------------------------------------------------------------------------
// Launcher (5 launches)
// ---------------------------------------------------------------------------
extern "C" void kernel_launch(void* const* d_in, const int* in_sizes, int n_in,
                              void* d_out, int out_size)
{
    const float* query = (const float*)d_in[0];
    const float* key_  = (const float*)d_in[1];
    const float* value = (const float*)d_in[2];
    const float* w_q   = (const float*)d_in[3];
    const float* w_k   = (const float*)d_in[4];
    const float* w_v   = (const float*)d_in[5];
    const float* w_o   = (const float*)d_in[6];
    const float* b_o   = (const float*)d_in[7];
    float* out = (float*)d_out;

    cudaFuncSetAttribute(gemm_qkv, cudaFuncAttributeMaxDynamicSharedMemorySize, GSMEM);
    cudaFuncSetAttribute(gemm_out, cudaFuncAttributeMaxDynamicSharedMemorySize, GSMEM);
    cudaFuncSetAttribute(attn_mma, cudaFuncAttributeMaxDynamicSharedMemorySize, ATT_SMEM);

    const int actN4 = (M_ROWS * D_) / 4;   // 2097152 -> 8192 blocks
    const int wN4   = (D_ * D_) / 4;       // 262144  -> 1024 blocks

    split_acts<<<dim3(actN4 / 256, 3), 256>>>(query, key_, value);
    split_w<<<dim3(wN4 / 256, 4), 256>>>(w_q, w_k, w_v, w_o);

    gemm_qkv<<<dim3(D_ / 128, M_ROWS / 128, 3), 256, GSMEM>>>();

    attn_mma<<<dim3(S_ / 128, B_ * H_), 256, ATT_SMEM>>>();

    gemm_out<<<dim3(D_ / 128, M_ROWS / 128), 256, GSMEM>>>(b_o, out);
}

// round 17
// speedup vs baseline: 7.1282x; 1.2427x over previous
#include <cuda_runtime.h>
#include <cuda_fp16.h>
#include <math.h>
#include <stdint.h>

// Problem constants
#define B_   4
#define S_   2048
#define D_   1024
#define H_   16
#define DK_  64
#define M_ROWS (B_ * S_)      // 8192

// ---------------------------------------------------------------------------
// Scratch (device globals; no allocation allowed)
// ---------------------------------------------------------------------------
__device__ __half g_a0h[(size_t)M_ROWS * D_];
__device__ __half g_a1h[(size_t)M_ROWS * D_];
__device__ __half g_a2h[(size_t)M_ROWS * D_];
__device__ __half g_w0h[(size_t)D_ * D_], g_w1h[(size_t)D_ * D_];
__device__ __half g_w2h[(size_t)D_ * D_], g_w3h[(size_t)D_ * D_];
__device__ __half g_qh[(size_t)M_ROWS * D_];
__device__ __half g_kh[(size_t)M_ROWS * D_], g_vh[(size_t)M_ROWS * D_];
__device__ __half g_cxh[(size_t)M_ROWS * D_];

// ---------------------------------------------------------------------------
// Helpers (baseline PTX only — NO tcgen05)
// ---------------------------------------------------------------------------
__device__ __forceinline__ uint32_t smem_u32(const void* p) {
    uint32_t a;
    asm("{ .reg .u64 t; cvta.to.shared.u64 t, %1; cvt.u32.u64 %0, t; }"
        : "=r"(a) : "l"(p));
    return a;
}

__device__ __forceinline__ void cp16(uint32_t dst, const void* src) {
    asm volatile("cp.async.cg.shared.global [%0], [%1], 16;" :: "r"(dst), "l"(src));
}

__device__ __forceinline__ void ldm4(uint32_t* r, uint32_t addr) {
    asm volatile("ldmatrix.sync.aligned.m8n8.x4.shared.b16 {%0,%1,%2,%3}, [%4];"
                 : "=r"(r[0]), "=r"(r[1]), "=r"(r[2]), "=r"(r[3]) : "r"(addr));
}

__device__ __forceinline__ void ldm4t(uint32_t* r, uint32_t addr) {
    asm volatile("ldmatrix.sync.aligned.m8n8.x4.trans.shared.b16 {%0,%1,%2,%3}, [%4];"
                 : "=r"(r[0]), "=r"(r[1]), "=r"(r[2]), "=r"(r[3]) : "r"(addr));
}

__device__ __forceinline__ void mma16816(float* d, const uint32_t* a, const uint32_t* b) {
    asm volatile(
        "mma.sync.aligned.m16n8k16.row.col.f32.f16.f16.f32 "
        "{%0,%1,%2,%3}, {%4,%5,%6,%7}, {%8,%9}, {%0,%1,%2,%3};"
        : "+f"(d[0]), "+f"(d[1]), "+f"(d[2]), "+f"(d[3])
        : "r"(a[0]), "r"(a[1]), "r"(a[2]), "r"(a[3]), "r"(b[0]), "r"(b[1]));
}

__device__ __forceinline__ uint32_t pack_f16x2(float a, float b) {
    __half2 h = __floats2half2_rn(a, b);
    return *(uint32_t*)&h;
}

// ---------------------------------------------------------------------------
// Batched hi-only splits (acts + weights)
// ---------------------------------------------------------------------------
__global__ __launch_bounds__(256)
void split_acts(const float* __restrict__ q, const float* __restrict__ k,
                const float* __restrict__ v)
{
    const int i = blockIdx.x * 256 + threadIdx.x;
    const float* in;
    __half* hi;
    if (blockIdx.y == 0)      { in = q; hi = g_a0h; }
    else if (blockIdx.y == 1) { in = k; hi = g_a1h; }
    else                      { in = v; hi = g_a2h; }
    float4 val = ((const float4*)in)[i];
    ((uint32_t*)hi)[2 * i]     = pack_f16x2(val.x, val.y);
    ((uint32_t*)hi)[2 * i + 1] = pack_f16x2(val.z, val.w);
}

__global__ __launch_bounds__(256)
void split_w(const float* __restrict__ wq, const float* __restrict__ wk,
             const float* __restrict__ wv, const float* __restrict__ wo)
{
    const int i = blockIdx.x * 256 + threadIdx.x;
    const float* in;
    __half* hi;
    if (blockIdx.y == 0)      { in = wq; hi = g_w0h; }
    else if (blockIdx.y == 1) { in = wk; hi = g_w1h; }
    else if (blockIdx.y == 2) { in = wv; hi = g_w2h; }
    else                      { in = wo; hi = g_w3h; }
    float4 v = ((const float4*)in)[i];
    ((uint32_t*)hi)[2 * i]     = pack_f16x2(v.x, v.y);
    ((uint32_t*)hi)[2 * i + 1] = pack_f16x2(v.z, v.w);
}

// ---------------------------------------------------------------------------
// GEMM core: 128x128 tile, BK=32, 3-stage cp.async, 1 sync per chunk.
// C = Ah * Bh^T into fp32 acc[4][4][4]. (single-pass fp16)
// ---------------------------------------------------------------------------
#define GSTRIDE 40
#define MATB    (128 * GSTRIDE * 2)      // 10240
#define STAGEB  (2 * MATB)               // 20480 (Ah, Bh)
#define GSMEM   (3 * STAGEB)             // 61440
#define NCHUNK  (D_ / 32)                // 32

__device__ __forceinline__ void gemm_core(const __half* __restrict__ Ah,
                                          const __half* __restrict__ Bh,
                                          uint32_t sb, float acc[4][4][4])
{
    const int tid = threadIdx.x;
    const int lane = tid & 31;
    const int wid = tid >> 5;
    const int mBase = blockIdx.y * 128;
    const int nBase = blockIdx.x * 128;
    const int wm = (wid >> 2) * 64;
    const int wn = (wid & 3) * 32;

    const int lrow = tid >> 1;
    const int lch = (tid & 1) * 2;
    const __half* gAh = Ah + (size_t)(mBase + lrow) * D_ + lch * 8;
    const __half* gBh = Bh + (size_t)(nBase + lrow) * D_ + lch * 8;
    const uint32_t dsto = (uint32_t)(lrow * (GSTRIDE * 2) + lch * 16);

    const uint32_t a_rc = (uint32_t)((wm + (lane & 15)) * (GSTRIDE * 2) + (lane >> 4) * 16);
    const uint32_t b_rc = (uint32_t)((wn + (lane >> 4) * 8 + (lane & 7)) * (GSTRIDE * 2)
                                     + ((lane >> 3) & 1) * 16);

#define GPF(sidx, c) do { \
    const uint32_t s0_ = sb + (uint32_t)(sidx) * STAGEB; \
    const int kb_ = (c) * 32; \
    cp16(s0_ + dsto,             gAh + kb_); \
    cp16(s0_ + dsto + 16,        gAh + kb_ + 8); \
    cp16(s0_ + MATB + dsto,      gBh + kb_); \
    cp16(s0_ + MATB + dsto + 16, gBh + kb_ + 8); \
    asm volatile("cp.async.commit_group;" ::: "memory"); \
} while (0)

    GPF(0, 0);
    GPF(1, 1);

    int cur = 0, pf = 2;
    for (int c = 0; c < NCHUNK; ++c) {
        if (c < NCHUNK - 2)
            asm volatile("cp.async.wait_group 1;" ::: "memory");
        else
            asm volatile("cp.async.wait_group 0;" ::: "memory");
        __syncthreads();
        if (c + 2 < NCHUNK) GPF(pf, c + 2);

        const uint32_t sAh = sb + (uint32_t)cur * STAGEB;
        const uint32_t sBh = sAh + MATB;

#pragma unroll
        for (int ks = 0; ks < 2; ++ks) {
            const uint32_t kbyte = (uint32_t)(ks * 32);
            uint32_t bh[2][4];
#pragma unroll
            for (int nj = 0; nj < 2; ++nj) {
                const uint32_t boff = b_rc + kbyte + (uint32_t)(nj * 16 * GSTRIDE * 2);
                ldm4(bh[nj], sBh + boff);
            }
#pragma unroll
            for (int mi = 0; mi < 4; ++mi) {
                const uint32_t aoff = a_rc + kbyte + (uint32_t)(mi * 16 * GSTRIDE * 2);
                uint32_t ah[4];
                ldm4(ah, sAh + aoff);
#pragma unroll
                for (int n8 = 0; n8 < 4; ++n8) {
                    const uint32_t* bhf = &bh[n8 >> 1][(n8 & 1) * 2];
                    mma16816(acc[mi][n8], ah, bhf);
                }
            }
        }
        cur = (cur == 2) ? 0 : cur + 1;
        pf = (pf == 2) ? 0 : pf + 1;
    }
#undef GPF
}

// ---------------------------------------------------------------------------
// Fused QKV projection GEMM (blockIdx.z selects input/weight/output)
// All outputs hi-only fp16, scattered into [B,H,S,dk].
// ---------------------------------------------------------------------------
__global__ __launch_bounds__(256, 2)
void gemm_qkv()
{
    extern __shared__ char smc[];
    const uint32_t sb = smem_u32(smc);

    const __half *Ah, *Bh;
    __half* Chi;
    float scale;
    if (blockIdx.z == 0)      { Ah = g_a0h; Bh = g_w0h; Chi = g_qh; scale = 0.125f; }
    else if (blockIdx.z == 1) { Ah = g_a1h; Bh = g_w1h; Chi = g_kh; scale = 1.0f; }
    else                      { Ah = g_a2h; Bh = g_w2h; Chi = g_vh; scale = 1.0f; }

    float acc[4][4][4];
#pragma unroll
    for (int mi = 0; mi < 4; ++mi)
#pragma unroll
        for (int nj = 0; nj < 4; ++nj)
#pragma unroll
            for (int e = 0; e < 4; ++e) acc[mi][nj][e] = 0.0f;

    gemm_core(Ah, Bh, sb, acc);

    const int lane = threadIdx.x & 31;
    const int wid = threadIdx.x >> 5;
    const int mBase = blockIdx.y * 128;
    const int nBase = blockIdx.x * 128;
    const int wm = (wid >> 2) * 64;
    const int wn = (wid & 3) * 32;
    const int g = lane >> 2;
    const int i2 = (lane & 3) * 2;

#pragma unroll
    for (int mi = 0; mi < 4; ++mi) {
#pragma unroll
        for (int n8 = 0; n8 < 4; ++n8) {
            const int row0 = mBase + wm + mi * 16 + g;
            const int row1 = row0 + 8;
            const int col = nBase + wn + n8 * 8 + i2;
            const float v00 = acc[mi][n8][0] * scale, v01 = acc[mi][n8][1] * scale;
            const float v10 = acc[mi][n8][2] * scale, v11 = acc[mi][n8][3] * scale;
            const int h = col >> 6;
            const int d0 = col & 63;
            const int b0i = row0 >> 11, s0i = row0 & 2047;
            const int b1i = row1 >> 11, s1i = row1 & 2047;
            const size_t o0 = ((((size_t)(b0i * H_ + h)) * S_ + s0i) * DK_ + d0) >> 1;
            const size_t o1 = ((((size_t)(b1i * H_ + h)) * S_ + s1i) * DK_ + d0) >> 1;
            ((uint32_t*)Chi)[o0] = pack_f16x2(v00, v01);
            ((uint32_t*)Chi)[o1] = pack_f16x2(v10, v11);
        }
    }
}

// ---------------------------------------------------------------------------
// Output projection GEMM + bias -> fp32 out
// ---------------------------------------------------------------------------
__global__ __launch_bounds__(256, 2)
void gemm_out(const float* __restrict__ bias, float* __restrict__ out)
{
    extern __shared__ char smc[];
    const uint32_t sb = smem_u32(smc);

    float acc[4][4][4];
#pragma unroll
    for (int mi = 0; mi < 4; ++mi)
#pragma unroll
        for (int nj = 0; nj < 4; ++nj)
#pragma unroll
            for (int e = 0; e < 4; ++e) acc[mi][nj][e] = 0.0f;

    gemm_core(g_cxh, g_w3h, sb, acc);

    const int lane = threadIdx.x & 31;
    const int wid = threadIdx.x >> 5;
    const int mBase = blockIdx.y * 128;
    const int nBase = blockIdx.x * 128;
    const int wm = (wid >> 2) * 64;
    const int wn = (wid & 3) * 32;
    const int g = lane >> 2;
    const int i2 = (lane & 3) * 2;

#pragma unroll
    for (int mi = 0; mi < 4; ++mi) {
#pragma unroll
        for (int n8 = 0; n8 < 4; ++n8) {
            const int row0 = mBase + wm + mi * 16 + g;
            const int row1 = row0 + 8;
            const int col = nBase + wn + n8 * 8 + i2;
            const float bx = bias[col], by = bias[col + 1];
            float2 o0, o1;
            o0.x = acc[mi][n8][0] + bx; o0.y = acc[mi][n8][1] + by;
            o1.x = acc[mi][n8][2] + bx; o1.y = acc[mi][n8][3] + by;
            *(float2*)(out + (size_t)row0 * D_ + col) = o0;
            *(float2*)(out + (size_t)row1 * D_ + col) = o1;
        }
    }
}

// ---------------------------------------------------------------------------
// HMMA flash attention, all single-pass fp16 (Q, K, V, P hi-only).
// Swizzled 128B rows, 64-key tiles, 1 sync/iter, ctx written fp16 hi-only.
// smem: Q 16KB + 2 stages x (K 8KB + V 8KB) = 48KB.
// ---------------------------------------------------------------------------
#define ATT_SMEM 49152
#define SWZ(row, ch) ((uint32_t)((row) * 128 + ((((ch)) ^ ((row) & 7)) << 4)))

__global__ __launch_bounds__(256, 2)
void attn_mma()
{
    extern __shared__ char smc[];
    const uint32_t sb = smem_u32(smc);
    const int tid = threadIdx.x;
    const int lane = tid & 31;
    const int wid = tid >> 5;
    const int bh = blockIdx.y;          // 0..63
    const int qt = blockIdx.x;          // 0..15

    const size_t qoff = ((size_t)bh * S_ + qt * 128) * DK_;
    const size_t kvoff = (size_t)bh * S_ * DK_;

    // prologue: Q + K/V stage 0 — one commit group
    {
#pragma unroll
        for (int j = 0; j < 4; ++j) {
            const int task = tid + 256 * j;
            const int row = task >> 3, ch = task & 7;
            cp16(sb + SWZ(row, ch), g_qh + qoff + (size_t)row * DK_ + ch * 8);
        }
#pragma unroll
        for (int j = 0; j < 2; ++j) {
            const int task = tid + 256 * j;
            const int row = task >> 3, ch = task & 7;
            const uint32_t so = SWZ(row, ch);
            cp16(sb + 16384 + so,        g_kh + kvoff + (size_t)row * DK_ + ch * 8);
            cp16(sb + 16384 + 8192 + so, g_vh + kvoff + (size_t)row * DK_ + ch * 8);
        }
        asm volatile("cp.async.commit_group;" ::: "memory");
    }

    uint32_t qfh[4][4];
    float o[8][4];
#pragma unroll
    for (int f = 0; f < 8; ++f)
#pragma unroll
        for (int e = 0; e < 4; ++e) o[f][e] = 0.0f;
    float mrow[2] = {-INFINITY, -INFINITY};
    float lrow[2] = {0.0f, 0.0f};

    const int qrow = wid * 16 + (lane & 15);
    const int qch0 = lane >> 4;
    const int krow0 = ((lane >> 4) << 3) + (lane & 7);
    const int kch0 = (lane >> 3) & 1;
    const int vrow0 = lane & 15;
    const int vch0 = lane >> 4;

    for (int kt = 0; kt < 32; ++kt) {
        asm volatile("cp.async.wait_group 0;" ::: "memory");
        __syncthreads();

        if (kt == 0) {
#pragma unroll
            for (int kc = 0; kc < 4; ++kc)
                ldm4(qfh[kc], sb + SWZ(qrow, qch0 + kc * 2));
        }

        if (kt + 1 < 32) {
            const uint32_t st = sb + 16384 + (uint32_t)(((kt + 1) & 1) * 16384);
            const size_t base = kvoff + (size_t)(kt + 1) * 64 * DK_;
#pragma unroll
            for (int j = 0; j < 2; ++j) {
                const int task = tid + 256 * j;
                const int row = task >> 3, ch = task & 7;
                const uint32_t so = SWZ(row, ch);
                cp16(st + so,        g_kh + base + (size_t)row * DK_ + ch * 8);
                cp16(st + 8192 + so, g_vh + base + (size_t)row * DK_ + ch * 8);
            }
            asm volatile("cp.async.commit_group;" ::: "memory");
        }

        const uint32_t sK = sb + 16384 + (uint32_t)((kt & 1) * 16384);
        const uint32_t sV = sK + 8192;

        // ---- S = Q K^T over 64 keys (single pass) ----
        float sc[8][4];
#pragma unroll
        for (int f = 0; f < 8; ++f)
#pragma unroll
            for (int e = 0; e < 4; ++e) sc[f][e] = 0.0f;

#pragma unroll
        for (int kc = 0; kc < 4; ++kc) {
#pragma unroll
            for (int n16 = 0; n16 < 4; ++n16) {
                uint32_t kh4[4];
                ldm4(kh4, sK + SWZ(krow0 + n16 * 16, kch0 + kc * 2));
                mma16816(sc[2 * n16],     qfh[kc], kh4);
                mma16816(sc[2 * n16 + 1], qfh[kc], kh4 + 2);
            }
        }

        // ---- online softmax (rows g and g+8) ----
#pragma unroll
        for (int r = 0; r < 2; ++r) {
            const int e0 = r * 2, e1 = r * 2 + 1;
            float rmax = -INFINITY;
#pragma unroll
            for (int f = 0; f < 8; ++f)
                rmax = fmaxf(rmax, fmaxf(sc[f][e0], sc[f][e1]));
            rmax = fmaxf(rmax, __shfl_xor_sync(0xffffffffu, rmax, 1));
            rmax = fmaxf(rmax, __shfl_xor_sync(0xffffffffu, rmax, 2));
            const float mnew = fmaxf(mrow[r], rmax);
            const float corr = __expf(mrow[r] - mnew);
            float rsum = 0.0f;
#pragma unroll
            for (int f = 0; f < 8; ++f) {
                float p0 = __expf(sc[f][e0] - mnew);
                float p1 = __expf(sc[f][e1] - mnew);
                sc[f][e0] = p0; sc[f][e1] = p1;
                rsum += p0 + p1;
            }
            rsum += __shfl_xor_sync(0xffffffffu, rsum, 1);
            rsum += __shfl_xor_sync(0xffffffffu, rsum, 2);
            lrow[r] = lrow[r] * corr + rsum;
            mrow[r] = mnew;
#pragma unroll
            for (int f = 0; f < 8; ++f) {
                o[f][e0] *= corr;
                o[f][e1] *= corr;
            }
        }

        // ---- pack P into fp16 a-frags (hi only, in place over sc) ----
        uint32_t* pp = (uint32_t*)&sc[0][0];
#pragma unroll
        for (int kk = 0; kk < 4; ++kk) {
            const uint32_t h0 = pack_f16x2(sc[2 * kk][0],     sc[2 * kk][1]);
            const uint32_t h1 = pack_f16x2(sc[2 * kk][2],     sc[2 * kk][3]);
            const uint32_t h2 = pack_f16x2(sc[2 * kk + 1][0], sc[2 * kk + 1][1]);
            const uint32_t h3 = pack_f16x2(sc[2 * kk + 1][2], sc[2 * kk + 1][3]);
            pp[kk * 4 + 0] = h0; pp[kk * 4 + 1] = h1;
            pp[kk * 4 + 2] = h2; pp[kk * 4 + 3] = h3;
        }

        // ---- O += P V (single pass) ----
#pragma unroll
        for (int kk = 0; kk < 4; ++kk) {
            const uint32_t* aPh = &pp[kk * 4];
#pragma unroll
            for (int n16 = 0; n16 < 4; ++n16) {
                uint32_t vh4[4];
                ldm4t(vh4, sV + SWZ(vrow0 + kk * 16, vch0 + n16 * 2));
                mma16816(o[2 * n16],     aPh, vh4);
                mma16816(o[2 * n16 + 1], aPh, vh4 + 2);
            }
        }
    }

    // ---- epilogue: normalize and write ctx hi [B,S,D] ----
    const int bb = bh >> 4;
    const int hh = bh & 15;
    const int g = lane >> 2;
    const int i2 = (lane & 3) * 2;
    const int s0 = qt * 128 + wid * 16 + g;
    const int s1 = s0 + 8;
    const float inv0 = 1.0f / lrow[0];
    const float inv1 = 1.0f / lrow[1];
#pragma unroll
    for (int f = 0; f < 8; ++f) {
        const int d = f * 8 + i2;
        const size_t i0 = ((((size_t)(bb * S_ + s0)) * H_ + hh) * DK_ + d) >> 1;
        const size_t i1 = ((((size_t)(bb * S_ + s1)) * H_ + hh) * DK_ + d) >> 1;
        ((uint32_t*)g_cxh)[i0] = pack_f16x2(o[f][0] * inv0, o[f][1] * inv0);
        ((uint32_t*)g_cxh)[i1] = pack_f16x2(o[f][2] * inv1, o[f][3] * inv1);
    }
}

// ---------------------------------------------------------------------------
// Launcher (5 launches)
// ---------------------------------------------------------------------------
extern "C" void kernel_launch(void* const* d_in, const int* in_sizes, int n_in,
                              void* d_out, int out_size)
{
    const float* query = (const float*)d_in[0];
    const float* key_  = (const float*)d_in[1];
    const float* value = (const float*)d_in[2];
    const float* w_q   = (const float*)d_in[3];
    const float* w_k   = (const float*)d_in[4];
    const float* w_v   = (const float*)d_in[5];
    const float* w_o   = (const float*)d_in[6];
    const float* b_o   = (const float*)d_in[7];
    float* out = (float*)d_out;

    cudaFuncSetAttribute(gemm_qkv, cudaFuncAttributeMaxDynamicSharedMemorySize, GSMEM);
    cudaFuncSetAttribute(gemm_out, cudaFuncAttributeMaxDynamicSharedMemorySize, GSMEM);
    cudaFuncSetAttribute(attn_mma, cudaFuncAttributeMaxDynamicSharedMemorySize, ATT_SMEM);

    const int actN4 = (M_ROWS * D_) / 4;   // 2097152 -> 8192 blocks
    const int wN4   = (D_ * D_) / 4;       // 262144  -> 1024 blocks

    split_acts<<<dim3(actN4 / 256, 3), 256>>>(query, key_, value);
    split_w<<<dim3(wN4 / 256, 4), 256>>>(w_q, w_k, w_v, w_o);

    gemm_qkv<<<dim3(D_ / 128, M_ROWS / 128, 3), 256, GSMEM>>>();

    attn_mma<<<dim3(S_ / 128, B_ * H_), 256, ATT_SMEM>>>();

    gemm_out<<<dim3(D_ / 128, M_ROWS / 128), 256, GSMEM>>>(b_o, out);
}